// round 10
// baseline (speedup 1.0000x reference)
#include <cuda_runtime.h>
#include <cuda_bf16.h>
#include <math.h>
#include <stdint.h>

#define Bb 4
#define Ss 2048
#define Dd 2048
#define Hh 16
#define HDim 128
#define MROWS (Bb * Ss)  // 8192

// Scratch (allocation-free: device globals)
__device__ float g_Q[(size_t)Bb * Ss * Dd];
__device__ float g_K[(size_t)Bb * Ss * Dd];
__device__ float g_V[(size_t)Bb * Ss * Dd];
__device__ float g_C[(size_t)Bb * Ss * Dd];
__device__ float g_As[(size_t)MROWS * Dd];      // subj rounded to tf32
__device__ float g_Ao[(size_t)MROWS * Dd];      // obj rounded to tf32
__device__ float g_Wr[4][(size_t)Dd * Dd];      // weights rounded to tf32
__device__ float2 g_tab2[64 * Ss];              // [j][s] -> (cos, sin)

// ---------------------------------------------------------------------------
// helpers
// ---------------------------------------------------------------------------
__device__ __forceinline__ uint32_t smem_u32(const void* p) {
    uint32_t r;
    asm("{ .reg .u64 t; cvta.to.shared.u64 t, %1; cvt.u32.u64 %0, t; }"
        : "=r"(r) : "l"(p));
    return r;
}

#define CP_ASYNC16(smem, gptr) \
    asm volatile("cp.async.cg.shared.global [%0], [%1], 16;" \
                 :: "r"(smem), "l"(gptr) : "memory")
#define CP_COMMIT() asm volatile("cp.async.commit_group;" ::: "memory")
#define CP_WAIT(n)  asm volatile("cp.async.wait_group %0;" :: "n"(n) : "memory")

__device__ __forceinline__ uint32_t cvt_tf32(float x) {
    uint32_t r;
    asm("cvt.rna.tf32.f32 %0, %1;" : "=r"(r) : "f"(x));
    return r;
}

__device__ __forceinline__ void mma_m16n8k8(float* d, const uint32_t* a,
                                            uint32_t b0, uint32_t b1) {
    asm volatile(
        "mma.sync.aligned.m16n8k8.row.col.f32.tf32.tf32.f32 "
        "{%0,%1,%2,%3}, {%4,%5,%6,%7}, {%8,%9}, {%0,%1,%2,%3};"
        : "+f"(d[0]), "+f"(d[1]), "+f"(d[2]), "+f"(d[3])
        : "r"(a[0]), "r"(a[1]), "r"(a[2]), "r"(a[3]), "r"(b0), "r"(b1));
}

__device__ __forceinline__ void mma_bf16(float* d, const uint32_t* a,
                                         uint32_t b0, uint32_t b1) {
    asm volatile(
        "mma.sync.aligned.m16n8k16.row.col.f32.bf16.bf16.f32 "
        "{%0,%1,%2,%3}, {%4,%5,%6,%7}, {%8,%9}, {%0,%1,%2,%3};"
        : "+f"(d[0]), "+f"(d[1]), "+f"(d[2]), "+f"(d[3])
        : "r"(a[0]), "r"(a[1]), "r"(a[2]), "r"(a[3]), "r"(b0), "r"(b1));
}

// split (x,y) into packed bf16 hi pair + lo pair (x in low half)
__device__ __forceinline__ void split2(float x, float y,
                                       uint32_t& hi, uint32_t& lo) {
    __nv_bfloat162 h2 = __floats2bfloat162_rn(x, y);
    float hx = __bfloat162float(h2.x);
    float hy = __bfloat162float(h2.y);
    __nv_bfloat162 l2 = __floats2bfloat162_rn(x - hx, y - hy);
    hi = *reinterpret_cast<uint32_t*>(&h2);
    lo = *reinterpret_cast<uint32_t*>(&l2);
}

// ---------------------------------------------------------------------------
// Pre-round fp32 -> tf32-exact fp32 (RNA). n multiple of 4.
// ---------------------------------------------------------------------------
__global__ __launch_bounds__(256) void round_tf32_kernel(
    const float* __restrict__ src, float* __restrict__ dst, int n4)
{
    int i = blockIdx.x * blockDim.x + threadIdx.x;
    if (i >= n4) return;
    float4 v = ((const float4*)src)[i];
    uint4 o;
    o.x = cvt_tf32(v.x);
    o.y = cvt_tf32(v.y);
    o.z = cvt_tf32(v.z);
    o.w = cvt_tf32(v.w);
    ((uint4*)dst)[i] = o;
}

// ---------------------------------------------------------------------------
// tf32 mma.sync GEMM on PRE-ROUNDED A and W.
// C[8192,2048] = A @ W + bias; optional fused RoPE.
// BM=256, BN=128, BK=32; 8 warps, warp tile 64x64; 2-stage cp.async;
// 256 threads, 1 CTA/SM (106KB smem).
// ---------------------------------------------------------------------------
#define BKt 32
#define NKT (Dd / BKt)            // 64
#define GBM 256
#define SA_STRIDE 36
#define SB_STRIDE 136
#define SA_WORDS (GBM * SA_STRIDE)   // 9216
#define SB_WORDS (BKt * SB_STRIDE)   // 4352
#define STAGE_WORDS (SA_WORDS + SB_WORDS)
#define GEMM_SMEM (2 * STAGE_WORDS * 4)  // 108544 B

__global__ __launch_bounds__(256, 1) void gemm_tc_kernel(
    const float* __restrict__ A, const float* __restrict__ W,
    const float* __restrict__ bias, float* __restrict__ C, int doRope)
{
    extern __shared__ float sm[];
    const int tid = threadIdx.x;
    const int wid = tid >> 5;
    const int lane = tid & 31;
    const int rowBase = blockIdx.y * GBM;
    const int colBase = blockIdx.x * 128;

    const uint32_t sbase = smem_u32(sm);

    // global load mapping
    // A tile: 256 rows x 32 cols; thread -> row tid>>3 (+32i, i<8), f4col tid&7
    // B tile: 32 rows x 128 cols; thread -> row tid>>5 (+8i, i<4), f4col tid&31
    const float* aG = A + (size_t)(rowBase + (tid >> 3)) * Dd + (tid & 7) * 4;
    const float* bG = W + (size_t)(tid >> 5) * Dd + colBase + (tid & 31) * 4;
    const uint32_t aS = sbase + ((tid >> 3) * SA_STRIDE + (tid & 7) * 4) * 4;
    const uint32_t bS = sbase + (SA_WORDS + (tid >> 5) * SB_STRIDE + (tid & 31) * 4) * 4;

    const int wr = wid & 3;       // warp row group (64 rows)
    const int wc = wid >> 2;      // warp col group (64 cols)
    const int m0 = wr * 64;
    const int n0 = wc * 64;
    const int lg = lane >> 2;     // 0..7
    const int lc = lane & 3;      // 0..3

    float acc[4][8][4];
    #pragma unroll
    for (int mi = 0; mi < 4; mi++)
        #pragma unroll
        for (int ni = 0; ni < 8; ni++)
            #pragma unroll
            for (int r = 0; r < 4; r++) acc[mi][ni][r] = 0.f;

    {
        #pragma unroll
        for (int i = 0; i < 8; i++)
            CP_ASYNC16(aS + i * 32 * SA_STRIDE * 4, aG + (size_t)(32 * i) * Dd);
        #pragma unroll
        for (int i = 0; i < 4; i++)
            CP_ASYNC16(bS + i * 8 * SB_STRIDE * 4,  bG + (size_t)(8 * i) * Dd);
        CP_COMMIT();
    }

    for (int kt = 0; kt < NKT; kt++) {
        const int s = kt & 1;
        if (kt + 1 < NKT) {
            const int s2 = (kt + 1) & 1;
            const float* ag = aG + (kt + 1) * BKt;
            const float* bg = bG + (size_t)(kt + 1) * BKt * Dd;
            const uint32_t as = aS + s2 * STAGE_WORDS * 4;
            const uint32_t bs = bS + s2 * STAGE_WORDS * 4;
            #pragma unroll
            for (int i = 0; i < 8; i++)
                CP_ASYNC16(as + i * 32 * SA_STRIDE * 4, ag + (size_t)(32 * i) * Dd);
            #pragma unroll
            for (int i = 0; i < 4; i++)
                CP_ASYNC16(bs + i * 8 * SB_STRIDE * 4,  bg + (size_t)(8 * i) * Dd);
            CP_COMMIT();
            CP_WAIT(1);
        } else {
            CP_WAIT(0);
        }
        __syncthreads();

        const uint32_t* sAp = (const uint32_t*)(sm + s * STAGE_WORDS);
        const uint32_t* sBp = sAp + SA_WORDS;

        #pragma unroll
        for (int ks = 0; ks < 4; ks++) {
            const int k0 = ks * 8;
            uint32_t afr[4][4];
            #pragma unroll
            for (int mi = 0; mi < 4; mi++) {
                const int r = m0 + mi * 16 + lg;
                const int c = k0 + lc;
                afr[mi][0] = sAp[r * SA_STRIDE + c];
                afr[mi][1] = sAp[(r + 8) * SA_STRIDE + c];
                afr[mi][2] = sAp[r * SA_STRIDE + c + 4];
                afr[mi][3] = sAp[(r + 8) * SA_STRIDE + c + 4];
            }
            #pragma unroll
            for (int ni = 0; ni < 8; ni++) {
                const int col = n0 + ni * 8 + lg;
                uint32_t b0 = sBp[(k0 + lc) * SB_STRIDE + col];
                uint32_t b1 = sBp[(k0 + 4 + lc) * SB_STRIDE + col];
                #pragma unroll
                for (int mi = 0; mi < 4; mi++)
                    mma_m16n8k8(acc[mi][ni], afr[mi], b0, b1);
            }
        }
        __syncthreads();
    }

    #pragma unroll
    for (int mi = 0; mi < 4; mi++) {
        const int row = rowBase + m0 + mi * 16 + lg;
        #pragma unroll
        for (int ni = 0; ni < 8; ni++) {
            const int col = colBase + n0 + ni * 8 + 2 * lc;
            const float bv0 = __ldg(bias + col);
            const float bv1 = __ldg(bias + col + 1);
            const int jn = (col & 127) >> 1;

            #pragma unroll
            for (int half = 0; half < 2; half++) {
                const int r = row + half * 8;
                float x0 = acc[mi][ni][2 * half]     + bv0;
                float x1 = acc[mi][ni][2 * half + 1] + bv1;
                if (doRope) {
                    float2 cs = g_tab2[jn * Ss + (r & (Ss - 1))];
                    float y0 = x0 * cs.x - x1 * cs.y;
                    float y1 = x0 * cs.y + x1 * cs.x;
                    x0 = y0; x1 = y1;
                }
                *(float2*)(C + (size_t)r * Dd + col) = make_float2(x0, x1);
            }
        }
    }
}

// ---------------------------------------------------------------------------
// RoPE cos/sin table (fp64 for angle accuracy), layout [j][s]
// ---------------------------------------------------------------------------
__global__ void rope_table2_kernel(const float* __restrict__ base_p)
{
    int t = blockIdx.x * blockDim.x + threadIdx.x;
    if (t >= 64 * Ss) return;
    int j = t >> 11, s = t & (Ss - 1);
    double base = (double)(*base_p);
    double f = exp(-(double)j / 64.0 * log(base));
    double ang = (double)s * f;
    double sn, cs;
    sincos(ang, &sn, &cs);
    g_tab2[t] = make_float2((float)cs, (float)sn);
}

// ---------------------------------------------------------------------------
// Flash attention v3 (unchanged from R9): bf16 split (hi+lo, 3-term) MMA.
// CTA: 128-row Q tile, 512 threads (16 warps), 64-key tiles.
// ---------------------------------------------------------------------------
#define F3_QHI 0
#define F3_QLO (F3_QHI + 128 * 68)
#define F3_KHI (F3_QLO + 128 * 68)
#define F3_KLO (F3_KHI + 64 * 68)
#define F3_VHI (F3_KLO + 64 * 68)
#define F3_VLO (F3_VHI + 128 * 36)
#define F3_PHI (F3_VLO + 128 * 36)
#define F3_PLO (F3_PHI + 128 * 36)
#define F3_RM  (F3_PLO + 128 * 36)
#define F3_RS  (F3_RM + 256)
#define F3_WORDS (F3_RS + 256)
#define FLASH3_SMEM (F3_WORDS * 4)   // 180224 B

__global__ __launch_bounds__(512, 1) void flash3_kernel(
    const float* __restrict__ Q, const float* __restrict__ K,
    const float* __restrict__ V, float* __restrict__ O)
{
    extern __shared__ uint32_t smw[];
    float* sRedM = (float*)(smw + F3_RM);
    float* sRedS = (float*)(smw + F3_RS);

    const int qt = (Ss / 128 - 1) - blockIdx.x;   // big CTAs first
    const int h = blockIdx.y, b = blockIdx.z;
    const int tid = threadIdx.x;
    const int w = tid >> 5, lane = tid & 31;
    const int lg = lane >> 2, lc = lane & 3;
    const int wr = w & 7, wc = w >> 3;
    const int m0 = wr * 16;
    const int q0 = qt * 128;
    const float scale = 0.08838834764831845f;   // 1/sqrt(128), folded into Q

    const int rA = m0 + lg;
    const int rB = m0 + lg + 8;
    const int gRA = q0 + rA;
    const int gRB = q0 + rB;

    {
        const int row = tid >> 2;
        const float* qg = Q + (size_t)(b * Ss + q0 + row) * Dd + h * HDim;
        #pragma unroll
        for (int i = 0; i < 8; i++) {
            const int c4 = (tid & 3) + 4 * i;
            float4 v = *(const float4*)(qg + c4 * 4);
            v.x *= scale; v.y *= scale; v.z *= scale; v.w *= scale;
            uint32_t h0, l0, h1, l1;
            split2(v.x, v.y, h0, l0);
            split2(v.z, v.w, h1, l1);
            const int dp = c4 * 2;
            smw[F3_QHI + row * 68 + dp]     = h0;
            smw[F3_QHI + row * 68 + dp + 1] = h1;
            smw[F3_QLO + row * 68 + dp]     = l0;
            smw[F3_QLO + row * 68 + dp + 1] = l1;
        }
    }

    float mrow[2] = {-1e30f, -1e30f};
    float lrow[2] = {0.f, 0.f};
    float ofr[8][4];
    #pragma unroll
    for (int n = 0; n < 8; n++)
        #pragma unroll
        for (int r = 0; r < 4; r++) ofr[n][r] = 0.f;

    const int ktEnd = 2 * qt + 1;
    for (int kt = 0; kt <= ktEnd; kt++) {
        __syncthreads();

        {
            const int row = tid >> 3;
            const float* kg = K + (size_t)(b * Ss + kt * 64 + row) * Dd + h * HDim;
            #pragma unroll
            for (int i = 0; i < 4; i++) {
                const int c4 = (tid & 7) + 8 * i;
                float4 v = *(const float4*)(kg + c4 * 4);
                uint32_t h0, l0, h1, l1;
                split2(v.x, v.y, h0, l0);
                split2(v.z, v.w, h1, l1);
                const int dp = c4 * 2;
                smw[F3_KHI + row * 68 + dp]     = h0;
                smw[F3_KHI + row * 68 + dp + 1] = h1;
                smw[F3_KLO + row * 68 + dp]     = l0;
                smw[F3_KLO + row * 68 + dp + 1] = l1;
            }
        }
        {
            const int d2 = tid & 63;
            const int tp8 = tid >> 6;
            const float* vg = V + (size_t)(b * Ss + kt * 64) * Dd + h * HDim;
            #pragma unroll
            for (int i = 0; i < 4; i++) {
                const int tp = i * 8 + tp8;
                float2 a = *(const float2*)(vg + (size_t)(2 * tp) * Dd + 2 * d2);
                float2 c = *(const float2*)(vg + (size_t)(2 * tp + 1) * Dd + 2 * d2);
                uint32_t h0, l0, h1, l1;
                split2(a.x, c.x, h0, l0);
                split2(a.y, c.y, h1, l1);
                smw[F3_VHI + (2 * d2) * 36 + tp]     = h0;
                smw[F3_VHI + (2 * d2 + 1) * 36 + tp] = h1;
                smw[F3_VLO + (2 * d2) * 36 + tp]     = l0;
                smw[F3_VLO + (2 * d2 + 1) * 36 + tp] = l1;
            }
        }
        __syncthreads();

        float sfr[4][4];
        #pragma unroll
        for (int n = 0; n < 4; n++)
            #pragma unroll
            for (int r = 0; r < 4; r++) sfr[n][r] = 0.f;

        #pragma unroll
        for (int ks = 0; ks < 8; ks++) {
            const int kp = ks * 8;
            uint32_t ah[4], al[4];
            ah[0] = smw[F3_QHI + rA * 68 + kp + lc];
            ah[1] = smw[F3_QHI + rB * 68 + kp + lc];
            ah[2] = smw[F3_QHI + rA * 68 + kp + lc + 4];
            ah[3] = smw[F3_QHI + rB * 68 + kp + lc + 4];
            al[0] = smw[F3_QLO + rA * 68 + kp + lc];
            al[1] = smw[F3_QLO + rB * 68 + kp + lc];
            al[2] = smw[F3_QLO + rA * 68 + kp + lc + 4];
            al[3] = smw[F3_QLO + rB * 68 + kp + lc + 4];
            #pragma unroll
            for (int ni = 0; ni < 4; ni++) {
                const int j = wc * 32 + ni * 8 + lg;
                uint32_t bh0 = smw[F3_KHI + j * 68 + kp + lc];
                uint32_t bh1 = smw[F3_KHI + j * 68 + kp + lc + 4];
                uint32_t bl0 = smw[F3_KLO + j * 68 + kp + lc];
                uint32_t bl1 = smw[F3_KLO + j * 68 + kp + lc + 4];
                mma_bf16(sfr[ni], ah, bh0, bh1);
                mma_bf16(sfr[ni], ah, bl0, bl1);
                mma_bf16(sfr[ni], al, bh0, bh1);
            }
        }

        const bool diag = (kt >= 2 * qt);
        float vA = -1e30f, vB = -1e30f;
        #pragma unroll
        for (int ni = 0; ni < 4; ni++) {
            if (diag) {
                const int gc0 = kt * 64 + wc * 32 + ni * 8 + 2 * lc;
                if (gc0 > gRA)     sfr[ni][0] = -1e30f;
                if (gc0 + 1 > gRA) sfr[ni][1] = -1e30f;
                if (gc0 > gRB)     sfr[ni][2] = -1e30f;
                if (gc0 + 1 > gRB) sfr[ni][3] = -1e30f;
            }
            vA = fmaxf(vA, fmaxf(sfr[ni][0], sfr[ni][1]));
            vB = fmaxf(vB, fmaxf(sfr[ni][2], sfr[ni][3]));
        }
        vA = fmaxf(vA, __shfl_xor_sync(0xffffffffu, vA, 1));
        vA = fmaxf(vA, __shfl_xor_sync(0xffffffffu, vA, 2));
        vB = fmaxf(vB, __shfl_xor_sync(0xffffffffu, vB, 1));
        vB = fmaxf(vB, __shfl_xor_sync(0xffffffffu, vB, 2));
        if (lc == 0) {
            sRedM[wc * 128 + rA] = vA;
            sRedM[wc * 128 + rB] = vB;
        }
        __syncthreads();
        const float mtA = fmaxf(sRedM[rA], sRedM[128 + rA]);
        const float mtB = fmaxf(sRedM[rB], sRedM[128 + rB]);
        const float mnA = fmaxf(mrow[0], mtA);
        const float mnB = fmaxf(mrow[1], mtB);
        const float alA = __expf(mrow[0] - mnA);
        const float alB = __expf(mrow[1] - mnB);

        float sumA = 0.f, sumB = 0.f;
        #pragma unroll
        for (int ni = 0; ni < 4; ni++) {
            float p0 = __expf(sfr[ni][0] - mnA);
            float p1 = __expf(sfr[ni][1] - mnA);
            float p2 = __expf(sfr[ni][2] - mnB);
            float p3 = __expf(sfr[ni][3] - mnB);
            sumA += p0 + p1;
            sumB += p2 + p3;
            uint32_t hi, lo;
            const int colp = wc * 16 + ni * 4 + lc;
            split2(p0, p1, hi, lo);
            smw[F3_PHI + rA * 36 + colp] = hi;
            smw[F3_PLO + rA * 36 + colp] = lo;
            split2(p2, p3, hi, lo);
            smw[F3_PHI + rB * 36 + colp] = hi;
            smw[F3_PLO + rB * 36 + colp] = lo;
        }
        sumA += __shfl_xor_sync(0xffffffffu, sumA, 1);
        sumA += __shfl_xor_sync(0xffffffffu, sumA, 2);
        sumB += __shfl_xor_sync(0xffffffffu, sumB, 1);
        sumB += __shfl_xor_sync(0xffffffffu, sumB, 2);
        if (lc == 0) {
            sRedS[wc * 128 + rA] = sumA;
            sRedS[wc * 128 + rB] = sumB;
        }
        __syncthreads();
        lrow[0] = lrow[0] * alA + sRedS[rA] + sRedS[128 + rA];
        lrow[1] = lrow[1] * alB + sRedS[rB] + sRedS[128 + rB];
        mrow[0] = mnA;
        mrow[1] = mnB;
        #pragma unroll
        for (int n = 0; n < 8; n++) {
            ofr[n][0] *= alA; ofr[n][1] *= alA;
            ofr[n][2] *= alB; ofr[n][3] *= alB;
        }

        #pragma unroll
        for (int ks2 = 0; ks2 < 4; ks2++) {
            const int kp = ks2 * 8;
            uint32_t ah[4], al[4];
            ah[0] = smw[F3_PHI + rA * 36 + kp + lc];
            ah[1] = smw[F3_PHI + rB * 36 + kp + lc];
            ah[2] = smw[F3_PHI + rA * 36 + kp + lc + 4];
            ah[3] = smw[F3_PHI + rB * 36 + kp + lc + 4];
            al[0] = smw[F3_PLO + rA * 36 + kp + lc];
            al[1] = smw[F3_PLO + rB * 36 + kp + lc];
            al[2] = smw[F3_PLO + rA * 36 + kp + lc + 4];
            al[3] = smw[F3_PLO + rB * 36 + kp + lc + 4];
            #pragma unroll
            for (int ni = 0; ni < 8; ni++) {
                const int d = wc * 64 + ni * 8 + lg;
                uint32_t bh0 = smw[F3_VHI + d * 36 + kp + lc];
                uint32_t bh1 = smw[F3_VHI + d * 36 + kp + lc + 4];
                uint32_t bl0 = smw[F3_VLO + d * 36 + kp + lc];
                uint32_t bl1 = smw[F3_VLO + d * 36 + kp + lc + 4];
                mma_bf16(ofr[ni], ah, bh0, bh1);
                mma_bf16(ofr[ni], ah, bl0, bl1);
                mma_bf16(ofr[ni], al, bh0, bh1);
            }
        }
    }

    const float invA = 1.f / lrow[0];
    const float invB = 1.f / lrow[1];
    float* og = O + (size_t)(b * Ss + q0) * Dd + h * HDim;
    #pragma unroll
    for (int ni = 0; ni < 8; ni++) {
        const int col = wc * 64 + ni * 8 + 2 * lc;
        float2 oA, oB;
        oA.x = __uint_as_float(cvt_tf32(ofr[ni][0] * invA));
        oA.y = __uint_as_float(cvt_tf32(ofr[ni][1] * invA));
        oB.x = __uint_as_float(cvt_tf32(ofr[ni][2] * invB));
        oB.y = __uint_as_float(cvt_tf32(ofr[ni][3] * invB));
        *(float2*)(og + (size_t)rA * Dd + col) = oA;
        *(float2*)(og + (size_t)rB * Dd + col) = oB;
    }
}

// ---------------------------------------------------------------------------
extern "C" void kernel_launch(void* const* d_in, const int* in_sizes, int n_in,
                              void* d_out, int out_size)
{
    const float* subj = (const float*)d_in[0];
    const float* obj  = (const float*)d_in[1];
    const float* wq   = (const float*)d_in[2];
    const float* bq   = (const float*)d_in[3];
    const float* wk   = (const float*)d_in[4];
    const float* bk   = (const float*)d_in[5];
    const float* wv   = (const float*)d_in[6];
    const float* bv   = (const float*)d_in[7];
    const float* wc   = (const float*)d_in[8];
    const float* bc   = (const float*)d_in[9];
    const float* base = (const float*)d_in[10];
    float* out = (float*)d_out;

    float *Q, *K, *V, *C, *As, *Ao, *Wr;
    cudaGetSymbolAddress((void**)&Q, g_Q);
    cudaGetSymbolAddress((void**)&K, g_K);
    cudaGetSymbolAddress((void**)&V, g_V);
    cudaGetSymbolAddress((void**)&C, g_C);
    cudaGetSymbolAddress((void**)&As, g_As);
    cudaGetSymbolAddress((void**)&Ao, g_Ao);
    cudaGetSymbolAddress((void**)&Wr, g_Wr);
    const size_t WSZ = (size_t)Dd * Dd;

    cudaFuncSetAttribute(gemm_tc_kernel,
                         cudaFuncAttributeMaxDynamicSharedMemorySize, GEMM_SMEM);
    cudaFuncSetAttribute(flash3_kernel,
                         cudaFuncAttributeMaxDynamicSharedMemorySize, FLASH3_SMEM);

    rope_table2_kernel<<<(64 * Ss + 255) / 256, 256>>>(base);

    const int nA4 = (int)((size_t)MROWS * Dd / 4);
    const int nW4 = (int)(WSZ / 4);
    round_tf32_kernel<<<(nA4 + 255) / 256, 256>>>(subj, As, nA4);
    round_tf32_kernel<<<(nA4 + 255) / 256, 256>>>(obj,  Ao, nA4);
    round_tf32_kernel<<<(nW4 + 255) / 256, 256>>>(wq, Wr + 0 * WSZ, nW4);
    round_tf32_kernel<<<(nW4 + 255) / 256, 256>>>(wk, Wr + 1 * WSZ, nW4);
    round_tf32_kernel<<<(nW4 + 255) / 256, 256>>>(wv, Wr + 2 * WSZ, nW4);
    round_tf32_kernel<<<(nW4 + 255) / 256, 256>>>(wc, Wr + 3 * WSZ, nW4);

    dim3 gg(Dd / 128, MROWS / GBM);
    gemm_tc_kernel<<<gg, 256, GEMM_SMEM>>>(As, Wr + 0 * WSZ, bq, Q, 1);
    gemm_tc_kernel<<<gg, 256, GEMM_SMEM>>>(Ao, Wr + 1 * WSZ, bk, K, 1);
    gemm_tc_kernel<<<gg, 256, GEMM_SMEM>>>(Ao, Wr + 2 * WSZ, bv, V, 0);

    flash3_kernel<<<dim3(Ss / 128, Hh, Bb), 512, FLASH3_SMEM>>>(Q, K, V, C);

    gemm_tc_kernel<<<gg, 256, GEMM_SMEM>>>(C, Wr + 3 * WSZ, bc, out, 0);
}

// round 11
// speedup vs baseline: 1.1364x; 1.1364x over previous
#include <cuda_runtime.h>
#include <cuda_bf16.h>
#include <math.h>
#include <stdint.h>

#define Bb 4
#define Ss 2048
#define Dd 2048
#define Hh 16
#define HDim 128
#define MROWS (Bb * Ss)  // 8192

// Scratch (allocation-free: device globals)
__device__ float g_Q[(size_t)Bb * Ss * Dd];
__device__ float g_K[(size_t)Bb * Ss * Dd];
__device__ float g_V[(size_t)Bb * Ss * Dd];
__device__ float g_C[(size_t)Bb * Ss * Dd];
__device__ float g_As[(size_t)MROWS * Dd];      // subj rounded to tf32
__device__ float g_Ao[(size_t)MROWS * Dd];      // obj rounded to tf32
__device__ float g_Wr[4][(size_t)Dd * Dd];      // weights rounded to tf32
__device__ float2 g_tab2[64 * Ss];              // [j][s] -> (cos, sin)

// ---------------------------------------------------------------------------
// helpers
// ---------------------------------------------------------------------------
__device__ __forceinline__ uint32_t smem_u32(const void* p) {
    uint32_t r;
    asm("{ .reg .u64 t; cvta.to.shared.u64 t, %1; cvt.u32.u64 %0, t; }"
        : "=r"(r) : "l"(p));
    return r;
}

#define CP_ASYNC16(smem, gptr) \
    asm volatile("cp.async.cg.shared.global [%0], [%1], 16;" \
                 :: "r"(smem), "l"(gptr) : "memory")
#define CP_COMMIT() asm volatile("cp.async.commit_group;" ::: "memory")
#define CP_WAIT(n)  asm volatile("cp.async.wait_group %0;" :: "n"(n) : "memory")

__device__ __forceinline__ uint32_t cvt_tf32(float x) {
    uint32_t r;
    asm("cvt.rna.tf32.f32 %0, %1;" : "=r"(r) : "f"(x));
    return r;
}

__device__ __forceinline__ void mma_m16n8k8(float* d, const uint32_t* a,
                                            uint32_t b0, uint32_t b1) {
    asm volatile(
        "mma.sync.aligned.m16n8k8.row.col.f32.tf32.tf32.f32 "
        "{%0,%1,%2,%3}, {%4,%5,%6,%7}, {%8,%9}, {%0,%1,%2,%3};"
        : "+f"(d[0]), "+f"(d[1]), "+f"(d[2]), "+f"(d[3])
        : "r"(a[0]), "r"(a[1]), "r"(a[2]), "r"(a[3]), "r"(b0), "r"(b1));
}

__device__ __forceinline__ void mma_bf16(float* d, const uint32_t* a,
                                         uint32_t b0, uint32_t b1) {
    asm volatile(
        "mma.sync.aligned.m16n8k16.row.col.f32.bf16.bf16.f32 "
        "{%0,%1,%2,%3}, {%4,%5,%6,%7}, {%8,%9}, {%0,%1,%2,%3};"
        : "+f"(d[0]), "+f"(d[1]), "+f"(d[2]), "+f"(d[3])
        : "r"(a[0]), "r"(a[1]), "r"(a[2]), "r"(a[3]), "r"(b0), "r"(b1));
}

// split (x,y) into packed bf16 hi pair + lo pair (x in low half)
__device__ __forceinline__ void split2(float x, float y,
                                       uint32_t& hi, uint32_t& lo) {
    __nv_bfloat162 h2 = __floats2bfloat162_rn(x, y);
    float hx = __bfloat162float(h2.x);
    float hy = __bfloat162float(h2.y);
    __nv_bfloat162 l2 = __floats2bfloat162_rn(x - hx, y - hy);
    hi = *reinterpret_cast<uint32_t*>(&h2);
    lo = *reinterpret_cast<uint32_t*>(&l2);
}

// ---------------------------------------------------------------------------
// Pre-round fp32 -> tf32-exact fp32 (RNA). n multiple of 4.
// ---------------------------------------------------------------------------
__global__ __launch_bounds__(256) void round_tf32_kernel(
    const float* __restrict__ src, float* __restrict__ dst, int n4)
{
    int i = blockIdx.x * blockDim.x + threadIdx.x;
    if (i >= n4) return;
    float4 v = ((const float4*)src)[i];
    uint4 o;
    o.x = cvt_tf32(v.x);
    o.y = cvt_tf32(v.y);
    o.z = cvt_tf32(v.z);
    o.w = cvt_tf32(v.w);
    ((uint4*)dst)[i] = o;
}

// ---------------------------------------------------------------------------
// tf32 mma.sync GEMM on PRE-ROUNDED A and W.
// C[8192,2048] = A @ W + bias; optional fused RoPE.
// BM=BN=128, BK=32; 4 warps (128 thr), warp tile 64x64; 2-stage cp.async;
// 71.7KB smem -> 2 CTAs/SM (8 warps/SM) for cross-CTA latency cover.
// ---------------------------------------------------------------------------
#define BKt 32
#define NKT (Dd / BKt)            // 64
#define SA_STRIDE 36
#define SB_STRIDE 136
#define SA_WORDS (128 * SA_STRIDE)   // 4608
#define SB_WORDS (BKt * SB_STRIDE)   // 4352
#define STAGE_WORDS (SA_WORDS + SB_WORDS)
#define GEMM_SMEM (2 * STAGE_WORDS * 4)  // 71680 B

__global__ __launch_bounds__(128, 2) void gemm_tc_kernel(
    const float* __restrict__ A, const float* __restrict__ W,
    const float* __restrict__ bias, float* __restrict__ C, int doRope)
{
    extern __shared__ float sm[];
    const int tid = threadIdx.x;
    const int wid = tid >> 5;
    const int lane = tid & 31;
    const int rowBase = blockIdx.y * 128;
    const int colBase = blockIdx.x * 128;

    const uint32_t sbase = smem_u32(sm);

    // global load mapping (128 threads, 8 float4 each for A and for B)
    // A tile: 128 rows x 32 cols; thread -> row tid>>3 (+16i, i<8), f4col tid&7
    // B tile: 32 rows x 128 cols; thread -> row tid>>5 (+4i, i<8),  f4col tid&31
    const float* aG = A + (size_t)(rowBase + (tid >> 3)) * Dd + (tid & 7) * 4;
    const float* bG = W + (size_t)(tid >> 5) * Dd + colBase + (tid & 31) * 4;
    const uint32_t aS = sbase + ((tid >> 3) * SA_STRIDE + (tid & 7) * 4) * 4;
    const uint32_t bS = sbase + (SA_WORDS + (tid >> 5) * SB_STRIDE + (tid & 31) * 4) * 4;

    const int wr = wid & 1;       // warp row group (64 rows)
    const int wc = wid >> 1;      // warp col group (64 cols)
    const int m0 = wr * 64;
    const int n0 = wc * 64;
    const int lg = lane >> 2;     // 0..7
    const int lc = lane & 3;      // 0..3

    float acc[4][8][4];
    #pragma unroll
    for (int mi = 0; mi < 4; mi++)
        #pragma unroll
        for (int ni = 0; ni < 8; ni++)
            #pragma unroll
            for (int r = 0; r < 4; r++) acc[mi][ni][r] = 0.f;

    {
        #pragma unroll
        for (int i = 0; i < 8; i++) {
            CP_ASYNC16(aS + i * 16 * SA_STRIDE * 4, aG + (size_t)(16 * i) * Dd);
            CP_ASYNC16(bS + i * 4 * SB_STRIDE * 4,  bG + (size_t)(4 * i) * Dd);
        }
        CP_COMMIT();
    }

    for (int kt = 0; kt < NKT; kt++) {
        const int s = kt & 1;
        if (kt + 1 < NKT) {
            const int s2 = (kt + 1) & 1;
            const float* ag = aG + (kt + 1) * BKt;
            const float* bg = bG + (size_t)(kt + 1) * BKt * Dd;
            const uint32_t as = aS + s2 * STAGE_WORDS * 4;
            const uint32_t bs = bS + s2 * STAGE_WORDS * 4;
            #pragma unroll
            for (int i = 0; i < 8; i++) {
                CP_ASYNC16(as + i * 16 * SA_STRIDE * 4, ag + (size_t)(16 * i) * Dd);
                CP_ASYNC16(bs + i * 4 * SB_STRIDE * 4,  bg + (size_t)(4 * i) * Dd);
            }
            CP_COMMIT();
            CP_WAIT(1);
        } else {
            CP_WAIT(0);
        }
        __syncthreads();

        const uint32_t* sAp = (const uint32_t*)(sm + s * STAGE_WORDS);
        const uint32_t* sBp = sAp + SA_WORDS;

        #pragma unroll
        for (int ks = 0; ks < 4; ks++) {
            const int k0 = ks * 8;
            uint32_t afr[4][4];
            #pragma unroll
            for (int mi = 0; mi < 4; mi++) {
                const int r = m0 + mi * 16 + lg;
                const int c = k0 + lc;
                afr[mi][0] = sAp[r * SA_STRIDE + c];
                afr[mi][1] = sAp[(r + 8) * SA_STRIDE + c];
                afr[mi][2] = sAp[r * SA_STRIDE + c + 4];
                afr[mi][3] = sAp[(r + 8) * SA_STRIDE + c + 4];
            }
            #pragma unroll
            for (int ni = 0; ni < 8; ni++) {
                const int col = n0 + ni * 8 + lg;
                uint32_t b0 = sBp[(k0 + lc) * SB_STRIDE + col];
                uint32_t b1 = sBp[(k0 + 4 + lc) * SB_STRIDE + col];
                #pragma unroll
                for (int mi = 0; mi < 4; mi++)
                    mma_m16n8k8(acc[mi][ni], afr[mi], b0, b1);
            }
        }
        __syncthreads();
    }

    #pragma unroll
    for (int mi = 0; mi < 4; mi++) {
        const int row = rowBase + m0 + mi * 16 + lg;
        #pragma unroll
        for (int ni = 0; ni < 8; ni++) {
            const int col = colBase + n0 + ni * 8 + 2 * lc;
            const float bv0 = __ldg(bias + col);
            const float bv1 = __ldg(bias + col + 1);
            const int jn = (col & 127) >> 1;

            #pragma unroll
            for (int half = 0; half < 2; half++) {
                const int r = row + half * 8;
                float x0 = acc[mi][ni][2 * half]     + bv0;
                float x1 = acc[mi][ni][2 * half + 1] + bv1;
                if (doRope) {
                    float2 cs = g_tab2[jn * Ss + (r & (Ss - 1))];
                    float y0 = x0 * cs.x - x1 * cs.y;
                    float y1 = x0 * cs.y + x1 * cs.x;
                    x0 = y0; x1 = y1;
                }
                *(float2*)(C + (size_t)r * Dd + col) = make_float2(x0, x1);
            }
        }
    }
}

// ---------------------------------------------------------------------------
// RoPE cos/sin table (fp64 for angle accuracy), layout [j][s]
// ---------------------------------------------------------------------------
__global__ void rope_table2_kernel(const float* __restrict__ base_p)
{
    int t = blockIdx.x * blockDim.x + threadIdx.x;
    if (t >= 64 * Ss) return;
    int j = t >> 11, s = t & (Ss - 1);
    double base = (double)(*base_p);
    double f = exp(-(double)j / 64.0 * log(base));
    double ang = (double)s * f;
    double sn, cs;
    sincos(ang, &sn, &cs);
    g_tab2[t] = make_float2((float)cs, (float)sn);
}

// ---------------------------------------------------------------------------
// Flash attention v3 (unchanged from R9): bf16 split (hi+lo, 3-term) MMA.
// CTA: 128-row Q tile, 512 threads (16 warps), 64-key tiles.
// ---------------------------------------------------------------------------
#define F3_QHI 0
#define F3_QLO (F3_QHI + 128 * 68)
#define F3_KHI (F3_QLO + 128 * 68)
#define F3_KLO (F3_KHI + 64 * 68)
#define F3_VHI (F3_KLO + 64 * 68)
#define F3_VLO (F3_VHI + 128 * 36)
#define F3_PHI (F3_VLO + 128 * 36)
#define F3_PLO (F3_PHI + 128 * 36)
#define F3_RM  (F3_PLO + 128 * 36)
#define F3_RS  (F3_RM + 256)
#define F3_WORDS (F3_RS + 256)
#define FLASH3_SMEM (F3_WORDS * 4)   // 180224 B

__global__ __launch_bounds__(512, 1) void flash3_kernel(
    const float* __restrict__ Q, const float* __restrict__ K,
    const float* __restrict__ V, float* __restrict__ O)
{
    extern __shared__ uint32_t smw[];
    float* sRedM = (float*)(smw + F3_RM);
    float* sRedS = (float*)(smw + F3_RS);

    const int qt = (Ss / 128 - 1) - blockIdx.x;   // big CTAs first
    const int h = blockIdx.y, b = blockIdx.z;
    const int tid = threadIdx.x;
    const int w = tid >> 5, lane = tid & 31;
    const int lg = lane >> 2, lc = lane & 3;
    const int wr = w & 7, wc = w >> 3;
    const int m0 = wr * 16;
    const int q0 = qt * 128;
    const float scale = 0.08838834764831845f;   // 1/sqrt(128), folded into Q

    const int rA = m0 + lg;
    const int rB = m0 + lg + 8;
    const int gRA = q0 + rA;
    const int gRB = q0 + rB;

    {
        const int row = tid >> 2;
        const float* qg = Q + (size_t)(b * Ss + q0 + row) * Dd + h * HDim;
        #pragma unroll
        for (int i = 0; i < 8; i++) {
            const int c4 = (tid & 3) + 4 * i;
            float4 v = *(const float4*)(qg + c4 * 4);
            v.x *= scale; v.y *= scale; v.z *= scale; v.w *= scale;
            uint32_t h0, l0, h1, l1;
            split2(v.x, v.y, h0, l0);
            split2(v.z, v.w, h1, l1);
            const int dp = c4 * 2;
            smw[F3_QHI + row * 68 + dp]     = h0;
            smw[F3_QHI + row * 68 + dp + 1] = h1;
            smw[F3_QLO + row * 68 + dp]     = l0;
            smw[F3_QLO + row * 68 + dp + 1] = l1;
        }
    }

    float mrow[2] = {-1e30f, -1e30f};
    float lrow[2] = {0.f, 0.f};
    float ofr[8][4];
    #pragma unroll
    for (int n = 0; n < 8; n++)
        #pragma unroll
        for (int r = 0; r < 4; r++) ofr[n][r] = 0.f;

    const int ktEnd = 2 * qt + 1;
    for (int kt = 0; kt <= ktEnd; kt++) {
        __syncthreads();

        {
            const int row = tid >> 3;
            const float* kg = K + (size_t)(b * Ss + kt * 64 + row) * Dd + h * HDim;
            #pragma unroll
            for (int i = 0; i < 4; i++) {
                const int c4 = (tid & 7) + 8 * i;
                float4 v = *(const float4*)(kg + c4 * 4);
                uint32_t h0, l0, h1, l1;
                split2(v.x, v.y, h0, l0);
                split2(v.z, v.w, h1, l1);
                const int dp = c4 * 2;
                smw[F3_KHI + row * 68 + dp]     = h0;
                smw[F3_KHI + row * 68 + dp + 1] = h1;
                smw[F3_KLO + row * 68 + dp]     = l0;
                smw[F3_KLO + row * 68 + dp + 1] = l1;
            }
        }
        {
            const int d2 = tid & 63;
            const int tp8 = tid >> 6;
            const float* vg = V + (size_t)(b * Ss + kt * 64) * Dd + h * HDim;
            #pragma unroll
            for (int i = 0; i < 4; i++) {
                const int tp = i * 8 + tp8;
                float2 a = *(const float2*)(vg + (size_t)(2 * tp) * Dd + 2 * d2);
                float2 c = *(const float2*)(vg + (size_t)(2 * tp + 1) * Dd + 2 * d2);
                uint32_t h0, l0, h1, l1;
                split2(a.x, c.x, h0, l0);
                split2(a.y, c.y, h1, l1);
                smw[F3_VHI + (2 * d2) * 36 + tp]     = h0;
                smw[F3_VHI + (2 * d2 + 1) * 36 + tp] = h1;
                smw[F3_VLO + (2 * d2) * 36 + tp]     = l0;
                smw[F3_VLO + (2 * d2 + 1) * 36 + tp] = l1;
            }
        }
        __syncthreads();

        float sfr[4][4];
        #pragma unroll
        for (int n = 0; n < 4; n++)
            #pragma unroll
            for (int r = 0; r < 4; r++) sfr[n][r] = 0.f;

        #pragma unroll
        for (int ks = 0; ks < 8; ks++) {
            const int kp = ks * 8;
            uint32_t ah[4], al[4];
            ah[0] = smw[F3_QHI + rA * 68 + kp + lc];
            ah[1] = smw[F3_QHI + rB * 68 + kp + lc];
            ah[2] = smw[F3_QHI + rA * 68 + kp + lc + 4];
            ah[3] = smw[F3_QHI + rB * 68 + kp + lc + 4];
            al[0] = smw[F3_QLO + rA * 68 + kp + lc];
            al[1] = smw[F3_QLO + rB * 68 + kp + lc];
            al[2] = smw[F3_QLO + rA * 68 + kp + lc + 4];
            al[3] = smw[F3_QLO + rB * 68 + kp + lc + 4];
            #pragma unroll
            for (int ni = 0; ni < 4; ni++) {
                const int j = wc * 32 + ni * 8 + lg;
                uint32_t bh0 = smw[F3_KHI + j * 68 + kp + lc];
                uint32_t bh1 = smw[F3_KHI + j * 68 + kp + lc + 4];
                uint32_t bl0 = smw[F3_KLO + j * 68 + kp + lc];
                uint32_t bl1 = smw[F3_KLO + j * 68 + kp + lc + 4];
                mma_bf16(sfr[ni], ah, bh0, bh1);
                mma_bf16(sfr[ni], ah, bl0, bl1);
                mma_bf16(sfr[ni], al, bh0, bh1);
            }
        }

        const bool diag = (kt >= 2 * qt);
        float vA = -1e30f, vB = -1e30f;
        #pragma unroll
        for (int ni = 0; ni < 4; ni++) {
            if (diag) {
                const int gc0 = kt * 64 + wc * 32 + ni * 8 + 2 * lc;
                if (gc0 > gRA)     sfr[ni][0] = -1e30f;
                if (gc0 + 1 > gRA) sfr[ni][1] = -1e30f;
                if (gc0 > gRB)     sfr[ni][2] = -1e30f;
                if (gc0 + 1 > gRB) sfr[ni][3] = -1e30f;
            }
            vA = fmaxf(vA, fmaxf(sfr[ni][0], sfr[ni][1]));
            vB = fmaxf(vB, fmaxf(sfr[ni][2], sfr[ni][3]));
        }
        vA = fmaxf(vA, __shfl_xor_sync(0xffffffffu, vA, 1));
        vA = fmaxf(vA, __shfl_xor_sync(0xffffffffu, vA, 2));
        vB = fmaxf(vB, __shfl_xor_sync(0xffffffffu, vB, 1));
        vB = fmaxf(vB, __shfl_xor_sync(0xffffffffu, vB, 2));
        if (lc == 0) {
            sRedM[wc * 128 + rA] = vA;
            sRedM[wc * 128 + rB] = vB;
        }
        __syncthreads();
        const float mtA = fmaxf(sRedM[rA], sRedM[128 + rA]);
        const float mtB = fmaxf(sRedM[rB], sRedM[128 + rB]);
        const float mnA = fmaxf(mrow[0], mtA);
        const float mnB = fmaxf(mrow[1], mtB);
        const float alA = __expf(mrow[0] - mnA);
        const float alB = __expf(mrow[1] - mnB);

        float sumA = 0.f, sumB = 0.f;
        #pragma unroll
        for (int ni = 0; ni < 4; ni++) {
            float p0 = __expf(sfr[ni][0] - mnA);
            float p1 = __expf(sfr[ni][1] - mnA);
            float p2 = __expf(sfr[ni][2] - mnB);
            float p3 = __expf(sfr[ni][3] - mnB);
            sumA += p0 + p1;
            sumB += p2 + p3;
            uint32_t hi, lo;
            const int colp = wc * 16 + ni * 4 + lc;
            split2(p0, p1, hi, lo);
            smw[F3_PHI + rA * 36 + colp] = hi;
            smw[F3_PLO + rA * 36 + colp] = lo;
            split2(p2, p3, hi, lo);
            smw[F3_PHI + rB * 36 + colp] = hi;
            smw[F3_PLO + rB * 36 + colp] = lo;
        }
        sumA += __shfl_xor_sync(0xffffffffu, sumA, 1);
        sumA += __shfl_xor_sync(0xffffffffu, sumA, 2);
        sumB += __shfl_xor_sync(0xffffffffu, sumB, 1);
        sumB += __shfl_xor_sync(0xffffffffu, sumB, 2);
        if (lc == 0) {
            sRedS[wc * 128 + rA] = sumA;
            sRedS[wc * 128 + rB] = sumB;
        }
        __syncthreads();
        lrow[0] = lrow[0] * alA + sRedS[rA] + sRedS[128 + rA];
        lrow[1] = lrow[1] * alB + sRedS[rB] + sRedS[128 + rB];
        mrow[0] = mnA;
        mrow[1] = mnB;
        #pragma unroll
        for (int n = 0; n < 8; n++) {
            ofr[n][0] *= alA; ofr[n][1] *= alA;
            ofr[n][2] *= alB; ofr[n][3] *= alB;
        }

        #pragma unroll
        for (int ks2 = 0; ks2 < 4; ks2++) {
            const int kp = ks2 * 8;
            uint32_t ah[4], al[4];
            ah[0] = smw[F3_PHI + rA * 36 + kp + lc];
            ah[1] = smw[F3_PHI + rB * 36 + kp + lc];
            ah[2] = smw[F3_PHI + rA * 36 + kp + lc + 4];
            ah[3] = smw[F3_PHI + rB * 36 + kp + lc + 4];
            al[0] = smw[F3_PLO + rA * 36 + kp + lc];
            al[1] = smw[F3_PLO + rB * 36 + kp + lc];
            al[2] = smw[F3_PLO + rA * 36 + kp + lc + 4];
            al[3] = smw[F3_PLO + rB * 36 + kp + lc + 4];
            #pragma unroll
            for (int ni = 0; ni < 8; ni++) {
                const int d = wc * 64 + ni * 8 + lg;
                uint32_t bh0 = smw[F3_VHI + d * 36 + kp + lc];
                uint32_t bh1 = smw[F3_VHI + d * 36 + kp + lc + 4];
                uint32_t bl0 = smw[F3_VLO + d * 36 + kp + lc];
                uint32_t bl1 = smw[F3_VLO + d * 36 + kp + lc + 4];
                mma_bf16(ofr[ni], ah, bh0, bh1);
                mma_bf16(ofr[ni], ah, bl0, bl1);
                mma_bf16(ofr[ni], al, bh0, bh1);
            }
        }
    }

    const float invA = 1.f / lrow[0];
    const float invB = 1.f / lrow[1];
    float* og = O + (size_t)(b * Ss + q0) * Dd + h * HDim;
    #pragma unroll
    for (int ni = 0; ni < 8; ni++) {
        const int col = wc * 64 + ni * 8 + 2 * lc;
        float2 oA, oB;
        oA.x = __uint_as_float(cvt_tf32(ofr[ni][0] * invA));
        oA.y = __uint_as_float(cvt_tf32(ofr[ni][1] * invA));
        oB.x = __uint_as_float(cvt_tf32(ofr[ni][2] * invB));
        oB.y = __uint_as_float(cvt_tf32(ofr[ni][3] * invB));
        *(float2*)(og + (size_t)rA * Dd + col) = oA;
        *(float2*)(og + (size_t)rB * Dd + col) = oB;
    }
}

// ---------------------------------------------------------------------------
extern "C" void kernel_launch(void* const* d_in, const int* in_sizes, int n_in,
                              void* d_out, int out_size)
{
    const float* subj = (const float*)d_in[0];
    const float* obj  = (const float*)d_in[1];
    const float* wq   = (const float*)d_in[2];
    const float* bq   = (const float*)d_in[3];
    const float* wk   = (const float*)d_in[4];
    const float* bk   = (const float*)d_in[5];
    const float* wv   = (const float*)d_in[6];
    const float* bv   = (const float*)d_in[7];
    const float* wc   = (const float*)d_in[8];
    const float* bc   = (const float*)d_in[9];
    const float* base = (const float*)d_in[10];
    float* out = (float*)d_out;

    float *Q, *K, *V, *C, *As, *Ao, *Wr;
    cudaGetSymbolAddress((void**)&Q, g_Q);
    cudaGetSymbolAddress((void**)&K, g_K);
    cudaGetSymbolAddress((void**)&V, g_V);
    cudaGetSymbolAddress((void**)&C, g_C);
    cudaGetSymbolAddress((void**)&As, g_As);
    cudaGetSymbolAddress((void**)&Ao, g_Ao);
    cudaGetSymbolAddress((void**)&Wr, g_Wr);
    const size_t WSZ = (size_t)Dd * Dd;

    cudaFuncSetAttribute(gemm_tc_kernel,
                         cudaFuncAttributeMaxDynamicSharedMemorySize, GEMM_SMEM);
    cudaFuncSetAttribute(flash3_kernel,
                         cudaFuncAttributeMaxDynamicSharedMemorySize, FLASH3_SMEM);

    rope_table2_kernel<<<(64 * Ss + 255) / 256, 256>>>(base);

    const int nA4 = (int)((size_t)MROWS * Dd / 4);
    const int nW4 = (int)(WSZ / 4);
    round_tf32_kernel<<<(nA4 + 255) / 256, 256>>>(subj, As, nA4);
    round_tf32_kernel<<<(nA4 + 255) / 256, 256>>>(obj,  Ao, nA4);
    round_tf32_kernel<<<(nW4 + 255) / 256, 256>>>(wq, Wr + 0 * WSZ, nW4);
    round_tf32_kernel<<<(nW4 + 255) / 256, 256>>>(wk, Wr + 1 * WSZ, nW4);
    round_tf32_kernel<<<(nW4 + 255) / 256, 256>>>(wv, Wr + 2 * WSZ, nW4);
    round_tf32_kernel<<<(nW4 + 255) / 256, 256>>>(wc, Wr + 3 * WSZ, nW4);

    dim3 gg(Dd / 128, MROWS / 128);
    gemm_tc_kernel<<<gg, 128, GEMM_SMEM>>>(As, Wr + 0 * WSZ, bq, Q, 1);
    gemm_tc_kernel<<<gg, 128, GEMM_SMEM>>>(Ao, Wr + 1 * WSZ, bk, K, 1);
    gemm_tc_kernel<<<gg, 128, GEMM_SMEM>>>(Ao, Wr + 2 * WSZ, bv, V, 0);

    flash3_kernel<<<dim3(Ss / 128, Hh, Bb), 512, FLASH3_SMEM>>>(Q, K, V, C);

    gemm_tc_kernel<<<gg, 128, GEMM_SMEM>>>(C, Wr + 3 * WSZ, bc, out, 0);
}

// round 13
// speedup vs baseline: 1.1511x; 1.0130x over previous
#include <cuda_runtime.h>
#include <cuda_bf16.h>
#include <math.h>
#include <stdint.h>

#define Bb 4
#define Ss 2048
#define Dd 2048
#define Hh 16
#define HDim 128
#define MROWS (Bb * Ss)  // 8192

// Scratch (allocation-free: device globals)
__device__ float g_Q[(size_t)Bb * Ss * Dd];
__device__ float g_K[(size_t)Bb * Ss * Dd];
__device__ float g_V[(size_t)Bb * Ss * Dd];
__device__ float g_C[(size_t)Bb * Ss * Dd];
__device__ float g_As[(size_t)MROWS * Dd];      // subj rounded to tf32
__device__ float g_Ao[(size_t)MROWS * Dd];      // obj rounded to tf32
__device__ float g_Wr[4][(size_t)Dd * Dd];      // weights rounded to tf32
__device__ float2 g_tab2[64 * Ss];              // [j][s] -> (cos, sin)

// ---------------------------------------------------------------------------
// helpers
// ---------------------------------------------------------------------------
__device__ __forceinline__ uint32_t smem_u32(const void* p) {
    uint32_t r;
    asm("{ .reg .u64 t; cvta.to.shared.u64 t, %1; cvt.u32.u64 %0, t; }"
        : "=r"(r) : "l"(p));
    return r;
}

#define CP_ASYNC16(smem, gptr) \
    asm volatile("cp.async.cg.shared.global [%0], [%1], 16;" \
                 :: "r"(smem), "l"(gptr) : "memory")
#define CP_COMMIT() asm volatile("cp.async.commit_group;" ::: "memory")
#define CP_WAIT(n)  asm volatile("cp.async.wait_group %0;" :: "n"(n) : "memory")

__device__ __forceinline__ uint32_t cvt_tf32(float x) {
    uint32_t r;
    asm("cvt.rna.tf32.f32 %0, %1;" : "=r"(r) : "f"(x));
    return r;
}
__device__ __forceinline__ float rna_tf32f(float x) {
    return __uint_as_float(cvt_tf32(x));
}

__device__ __forceinline__ void mma_m16n8k8(float* d, const uint32_t* a,
                                            uint32_t b0, uint32_t b1) {
    asm volatile(
        "mma.sync.aligned.m16n8k8.row.col.f32.tf32.tf32.f32 "
        "{%0,%1,%2,%3}, {%4,%5,%6,%7}, {%8,%9}, {%0,%1,%2,%3};"
        : "+f"(d[0]), "+f"(d[1]), "+f"(d[2]), "+f"(d[3])
        : "r"(a[0]), "r"(a[1]), "r"(a[2]), "r"(a[3]), "r"(b0), "r"(b1));
}

__device__ __forceinline__ void mma_bf16(float* d, const uint32_t* a,
                                         uint32_t b0, uint32_t b1) {
    asm volatile(
        "mma.sync.aligned.m16n8k16.row.col.f32.bf16.bf16.f32 "
        "{%0,%1,%2,%3}, {%4,%5,%6,%7}, {%8,%9}, {%0,%1,%2,%3};"
        : "+f"(d[0]), "+f"(d[1]), "+f"(d[2]), "+f"(d[3])
        : "r"(a[0]), "r"(a[1]), "r"(a[2]), "r"(a[3]), "r"(b0), "r"(b1));
}

// split (x,y) into packed bf16 hi pair + lo pair (x in low half)
__device__ __forceinline__ void split2(float x, float y,
                                       uint32_t& hi, uint32_t& lo) {
    __nv_bfloat162 h2 = __floats2bfloat162_rn(x, y);
    float hx = __bfloat162float(h2.x);
    float hy = __bfloat162float(h2.y);
    __nv_bfloat162 l2 = __floats2bfloat162_rn(x - hx, y - hy);
    hi = *reinterpret_cast<uint32_t*>(&h2);
    lo = *reinterpret_cast<uint32_t*>(&l2);
}

// ---------------------------------------------------------------------------
// Pre-round fp32 -> tf32-exact fp32 (RNA). n multiple of 4.
// ---------------------------------------------------------------------------
__global__ __launch_bounds__(256) void round_tf32_kernel(
    const float* __restrict__ src, float* __restrict__ dst, int n4)
{
    int i = blockIdx.x * blockDim.x + threadIdx.x;
    if (i >= n4) return;
    float4 v = ((const float4*)src)[i];
    uint4 o;
    o.x = cvt_tf32(v.x);
    o.y = cvt_tf32(v.y);
    o.z = cvt_tf32(v.z);
    o.w = cvt_tf32(v.w);
    ((uint4*)dst)[i] = o;
}

// ---------------------------------------------------------------------------
// tf32 mma.sync GEMM on PRE-ROUNDED A and W.
// BM=BN=128, BK=32; 4 warps, warp tile 64x64; 3-stage cp.async;
// 107.5KB smem -> 2 CTAs/SM.
// ---------------------------------------------------------------------------
#define BKt 32
#define NKT (Dd / BKt)            // 64
#define GST 3
#define SA_STRIDE 36
#define SB_STRIDE 136
#define SA_WORDS (128 * SA_STRIDE)   // 4608
#define SB_WORDS (BKt * SB_STRIDE)   // 4352
#define STAGE_WORDS (SA_WORDS + SB_WORDS)
#define GEMM_SMEM (GST * STAGE_WORDS * 4)  // 107520 B

__global__ __launch_bounds__(128, 2) void gemm_tc_kernel(
    const float* __restrict__ A, const float* __restrict__ W,
    const float* __restrict__ bias, float* __restrict__ C, int doRope)
{
    extern __shared__ float sm[];
    const int tid = threadIdx.x;
    const int wid = tid >> 5;
    const int lane = tid & 31;
    const int rowBase = blockIdx.y * 128;
    const int colBase = blockIdx.x * 128;

    const uint32_t sbase = smem_u32(sm);

    const float* aG = A + (size_t)(rowBase + (tid >> 3)) * Dd + (tid & 7) * 4;
    const float* bG = W + (size_t)(tid >> 5) * Dd + colBase + (tid & 31) * 4;
    const uint32_t aS = sbase + ((tid >> 3) * SA_STRIDE + (tid & 7) * 4) * 4;
    const uint32_t bS = sbase + (SA_WORDS + (tid >> 5) * SB_STRIDE + (tid & 31) * 4) * 4;

    const int wr = wid & 1;
    const int wc = wid >> 1;
    const int m0 = wr * 64;
    const int n0 = wc * 64;
    const int lg = lane >> 2;
    const int lc = lane & 3;

    float acc[4][8][4];
    #pragma unroll
    for (int mi = 0; mi < 4; mi++)
        #pragma unroll
        for (int ni = 0; ni < 8; ni++)
            #pragma unroll
            for (int r = 0; r < 4; r++) acc[mi][ni][r] = 0.f;

    // prologue: stages 0 and 1
    #pragma unroll
    for (int p = 0; p < 2; p++) {
        const float* ag = aG + p * BKt;
        const float* bg = bG + (size_t)p * BKt * Dd;
        const uint32_t as = aS + p * STAGE_WORDS * 4;
        const uint32_t bs = bS + p * STAGE_WORDS * 4;
        #pragma unroll
        for (int i = 0; i < 8; i++) {
            CP_ASYNC16(as + i * 16 * SA_STRIDE * 4, ag + (size_t)(16 * i) * Dd);
            CP_ASYNC16(bs + i * 4 * SB_STRIDE * 4,  bg + (size_t)(4 * i) * Dd);
        }
        CP_COMMIT();
    }

    int s = 0;
    for (int kt = 0; kt < NKT; kt++) {
        if (kt + 2 < NKT) {
            int s2 = s + 2; if (s2 >= GST) s2 -= GST;
            const float* ag = aG + (kt + 2) * BKt;
            const float* bg = bG + (size_t)(kt + 2) * BKt * Dd;
            const uint32_t as = aS + s2 * STAGE_WORDS * 4;
            const uint32_t bs = bS + s2 * STAGE_WORDS * 4;
            #pragma unroll
            for (int i = 0; i < 8; i++) {
                CP_ASYNC16(as + i * 16 * SA_STRIDE * 4, ag + (size_t)(16 * i) * Dd);
                CP_ASYNC16(bs + i * 4 * SB_STRIDE * 4,  bg + (size_t)(4 * i) * Dd);
            }
            CP_COMMIT();
            CP_WAIT(2);
        } else if (kt + 1 < NKT) {
            CP_WAIT(1);
        } else {
            CP_WAIT(0);
        }
        __syncthreads();

        const uint32_t* sAp = (const uint32_t*)(sm + s * STAGE_WORDS);
        const uint32_t* sBp = sAp + SA_WORDS;

        #pragma unroll
        for (int ks = 0; ks < 4; ks++) {
            const int k0 = ks * 8;
            uint32_t afr[4][4];
            #pragma unroll
            for (int mi = 0; mi < 4; mi++) {
                const int r = m0 + mi * 16 + lg;
                const int c = k0 + lc;
                afr[mi][0] = sAp[r * SA_STRIDE + c];
                afr[mi][1] = sAp[(r + 8) * SA_STRIDE + c];
                afr[mi][2] = sAp[r * SA_STRIDE + c + 4];
                afr[mi][3] = sAp[(r + 8) * SA_STRIDE + c + 4];
            }
            #pragma unroll
            for (int ni = 0; ni < 8; ni++) {
                const int col = n0 + ni * 8 + lg;
                uint32_t b0 = sBp[(k0 + lc) * SB_STRIDE + col];
                uint32_t b1 = sBp[(k0 + 4 + lc) * SB_STRIDE + col];
                #pragma unroll
                for (int mi = 0; mi < 4; mi++)
                    mma_m16n8k8(acc[mi][ni], afr[mi], b0, b1);
            }
        }
        __syncthreads();
        if (++s >= GST) s -= GST;
    }

    #pragma unroll
    for (int mi = 0; mi < 4; mi++) {
        const int row = rowBase + m0 + mi * 16 + lg;
        #pragma unroll
        for (int ni = 0; ni < 8; ni++) {
            const int col = colBase + n0 + ni * 8 + 2 * lc;
            const float bv0 = __ldg(bias + col);
            const float bv1 = __ldg(bias + col + 1);
            const int jn = (col & 127) >> 1;

            #pragma unroll
            for (int half = 0; half < 2; half++) {
                const int r = row + half * 8;
                float x0 = acc[mi][ni][2 * half]     + bv0;
                float x1 = acc[mi][ni][2 * half + 1] + bv1;
                if (doRope) {
                    float2 cs = g_tab2[jn * Ss + (r & (Ss - 1))];
                    float y0 = x0 * cs.x - x1 * cs.y;
                    float y1 = x0 * cs.y + x1 * cs.x;
                    x0 = y0; x1 = y1;
                }
                *(float2*)(C + (size_t)r * Dd + col) = make_float2(x0, x1);
            }
        }
    }
}

// ---------------------------------------------------------------------------
// RoPE cos/sin table (fp64 for angle accuracy), layout [j][s]
// ---------------------------------------------------------------------------
__global__ void rope_table2_kernel(const float* __restrict__ base_p)
{
    int t = blockIdx.x * blockDim.x + threadIdx.x;
    if (t >= 64 * Ss) return;
    int j = t >> 11, s = t & (Ss - 1);
    double base = (double)(*base_p);
    double f = exp(-(double)j / 64.0 * log(base));
    double ang = (double)s * f;
    double sn, cs;
    sincos(ang, &sn, &cs);
    g_tab2[t] = make_float2((float)cs, (float)sn);
}

// ---------------------------------------------------------------------------
// Flash attention v4: QK = bf16 hi/lo 3-term; PV = tf32 (P,V RNA-rounded;
// row-sum l computed from the SAME rounded p -> consistent normalization).
// CTA: 128-row Q tile, 512 threads (16 warps), 64-key tiles.
// ---------------------------------------------------------------------------
#define F4_QHI 0
#define F4_QLO (F4_QHI + 128 * 68)
#define F4_KHI (F4_QLO + 128 * 68)
#define F4_KLO (F4_KHI + 64 * 68)
#define F4_V   (F4_KLO + 64 * 68)     // V[t][d] tf32 fp32, stride 132
#define F4_P   (F4_V + 64 * 132)      // P[row][t] tf32 fp32, stride 68
#define F4_RM  (F4_P + 128 * 68)
#define F4_RS  (F4_RM + 256)
#define F4_WORDS (F4_RS + 256)
#define FLASH4_SMEM (F4_WORDS * 4)    // 175104 B

__global__ __launch_bounds__(512, 1) void flash4_kernel(
    const float* __restrict__ Q, const float* __restrict__ K,
    const float* __restrict__ V, float* __restrict__ O)
{
    extern __shared__ uint32_t smw[];
    float* sRedM = (float*)(smw + F4_RM);
    float* sRedS = (float*)(smw + F4_RS);
    float* sP = (float*)(smw + F4_P);

    const int qt = (Ss / 128 - 1) - blockIdx.x;   // big CTAs first
    const int h = blockIdx.y, b = blockIdx.z;
    const int tid = threadIdx.x;
    const int w = tid >> 5, lane = tid & 31;
    const int lg = lane >> 2, lc = lane & 3;
    const int wr = w & 7, wc = w >> 3;
    const int m0 = wr * 16;
    const int q0 = qt * 128;
    const float scale = 0.08838834764831845f;   // 1/sqrt(128), folded into Q

    const int rA = m0 + lg;
    const int rB = m0 + lg + 8;
    const int gRA = q0 + rA;
    const int gRB = q0 + rB;

    // --- load Q tile (128x128), scale + split to bf16 hi/lo pairs ---
    {
        const int row = tid >> 2;
        const float* qg = Q + (size_t)(b * Ss + q0 + row) * Dd + h * HDim;
        #pragma unroll
        for (int i = 0; i < 8; i++) {
            const int c4 = (tid & 3) + 4 * i;
            float4 v = *(const float4*)(qg + c4 * 4);
            v.x *= scale; v.y *= scale; v.z *= scale; v.w *= scale;
            uint32_t h0, l0, h1, l1;
            split2(v.x, v.y, h0, l0);
            split2(v.z, v.w, h1, l1);
            const int dp = c4 * 2;
            smw[F4_QHI + row * 68 + dp]     = h0;
            smw[F4_QHI + row * 68 + dp + 1] = h1;
            smw[F4_QLO + row * 68 + dp]     = l0;
            smw[F4_QLO + row * 68 + dp + 1] = l1;
        }
    }

    float mrow[2] = {-1e30f, -1e30f};
    float lrow[2] = {0.f, 0.f};
    float ofr[8][4];
    #pragma unroll
    for (int n = 0; n < 8; n++)
        #pragma unroll
        for (int r = 0; r < 4; r++) ofr[n][r] = 0.f;

    const int ktEnd = 2 * qt + 1;
    for (int kt = 0; kt <= ktEnd; kt++) {
        __syncthreads();   // prev PV consumed sV/sP; Q store done (first iter)

        // --- load K tile (64x128), split hi/lo ---
        {
            const int row = tid >> 3;
            const float* kg = K + (size_t)(b * Ss + kt * 64 + row) * Dd + h * HDim;
            #pragma unroll
            for (int i = 0; i < 4; i++) {
                const int c4 = (tid & 7) + 8 * i;
                float4 v = *(const float4*)(kg + c4 * 4);
                uint32_t h0, l0, h1, l1;
                split2(v.x, v.y, h0, l0);
                split2(v.z, v.w, h1, l1);
                const int dp = c4 * 2;
                smw[F4_KHI + row * 68 + dp]     = h0;
                smw[F4_KHI + row * 68 + dp + 1] = h1;
                smw[F4_KLO + row * 68 + dp]     = l0;
                smw[F4_KLO + row * 68 + dp + 1] = l1;
            }
        }
        // --- load V tile (64x128) natural layout, RNA-round to tf32 ---
        {
            const int f4 = tid & 31;          // float4 column index
            const int r0v = tid >> 5;         // 0..15
            const float* vg = V + (size_t)(b * Ss + kt * 64) * Dd + h * HDim;
            #pragma unroll
            for (int i = 0; i < 4; i++) {
                const int row = r0v + 16 * i;
                float4 v = *(const float4*)(vg + (size_t)row * Dd + f4 * 4);
                uint4 o;
                o.x = cvt_tf32(v.x);
                o.y = cvt_tf32(v.y);
                o.z = cvt_tf32(v.z);
                o.w = cvt_tf32(v.w);
                *(uint4*)&smw[F4_V + row * 132 + f4 * 4] = o;
            }
        }
        __syncthreads();

        // --- S = Q @ K^T (3-term bf16): rows m0..+15, cols wc*32..+31
        float sfr[4][4];
        #pragma unroll
        for (int n = 0; n < 4; n++)
            #pragma unroll
            for (int r = 0; r < 4; r++) sfr[n][r] = 0.f;

        #pragma unroll
        for (int ks = 0; ks < 8; ks++) {
            const int kp = ks * 8;
            uint32_t ah[4], al[4];
            ah[0] = smw[F4_QHI + rA * 68 + kp + lc];
            ah[1] = smw[F4_QHI + rB * 68 + kp + lc];
            ah[2] = smw[F4_QHI + rA * 68 + kp + lc + 4];
            ah[3] = smw[F4_QHI + rB * 68 + kp + lc + 4];
            al[0] = smw[F4_QLO + rA * 68 + kp + lc];
            al[1] = smw[F4_QLO + rB * 68 + kp + lc];
            al[2] = smw[F4_QLO + rA * 68 + kp + lc + 4];
            al[3] = smw[F4_QLO + rB * 68 + kp + lc + 4];
            #pragma unroll
            for (int ni = 0; ni < 4; ni++) {
                const int j = wc * 32 + ni * 8 + lg;
                uint32_t bh0 = smw[F4_KHI + j * 68 + kp + lc];
                uint32_t bh1 = smw[F4_KHI + j * 68 + kp + lc + 4];
                uint32_t bl0 = smw[F4_KLO + j * 68 + kp + lc];
                uint32_t bl1 = smw[F4_KLO + j * 68 + kp + lc + 4];
                mma_bf16(sfr[ni], ah, bh0, bh1);
                mma_bf16(sfr[ni], ah, bl0, bl1);
                mma_bf16(sfr[ni], al, bh0, bh1);
            }
        }

        // --- online softmax on C-fragments ---
        const bool diag = (kt >= 2 * qt);
        float vA = -1e30f, vB = -1e30f;
        #pragma unroll
        for (int ni = 0; ni < 4; ni++) {
            if (diag) {
                const int gc0 = kt * 64 + wc * 32 + ni * 8 + 2 * lc;
                if (gc0 > gRA)     sfr[ni][0] = -1e30f;
                if (gc0 + 1 > gRA) sfr[ni][1] = -1e30f;
                if (gc0 > gRB)     sfr[ni][2] = -1e30f;
                if (gc0 + 1 > gRB) sfr[ni][3] = -1e30f;
            }
            vA = fmaxf(vA, fmaxf(sfr[ni][0], sfr[ni][1]));
            vB = fmaxf(vB, fmaxf(sfr[ni][2], sfr[ni][3]));
        }
        vA = fmaxf(vA, __shfl_xor_sync(0xffffffffu, vA, 1));
        vA = fmaxf(vA, __shfl_xor_sync(0xffffffffu, vA, 2));
        vB = fmaxf(vB, __shfl_xor_sync(0xffffffffu, vB, 1));
        vB = fmaxf(vB, __shfl_xor_sync(0xffffffffu, vB, 2));
        if (lc == 0) {
            sRedM[wc * 128 + rA] = vA;
            sRedM[wc * 128 + rB] = vB;
        }
        __syncthreads();
        const float mtA = fmaxf(sRedM[rA], sRedM[128 + rA]);
        const float mtB = fmaxf(sRedM[rB], sRedM[128 + rB]);
        const float mnA = fmaxf(mrow[0], mtA);
        const float mnB = fmaxf(mrow[1], mtB);
        const float alA = __expf(mrow[0] - mnA);
        const float alB = __expf(mrow[1] - mnB);

        float sumA = 0.f, sumB = 0.f;
        #pragma unroll
        for (int ni = 0; ni < 4; ni++) {
            // RNA-round p to tf32 and use the ROUNDED values for both the
            // stored P and the row-sum -> consistent normalization.
            float p0 = rna_tf32f(__expf(sfr[ni][0] - mnA));
            float p1 = rna_tf32f(__expf(sfr[ni][1] - mnA));
            float p2 = rna_tf32f(__expf(sfr[ni][2] - mnB));
            float p3 = rna_tf32f(__expf(sfr[ni][3] - mnB));
            sumA += p0 + p1;
            sumB += p2 + p3;
            const int t0 = wc * 32 + ni * 8 + 2 * lc;
            *(float2*)&sP[rA * 68 + t0] = make_float2(p0, p1);
            *(float2*)&sP[rB * 68 + t0] = make_float2(p2, p3);
        }
        sumA += __shfl_xor_sync(0xffffffffu, sumA, 1);
        sumA += __shfl_xor_sync(0xffffffffu, sumA, 2);
        sumB += __shfl_xor_sync(0xffffffffu, sumB, 1);
        sumB += __shfl_xor_sync(0xffffffffu, sumB, 2);
        if (lc == 0) {
            sRedS[wc * 128 + rA] = sumA;
            sRedS[wc * 128 + rB] = sumB;
        }
        __syncthreads();   // also publishes P
        lrow[0] = lrow[0] * alA + sRedS[rA] + sRedS[128 + rA];
        lrow[1] = lrow[1] * alB + sRedS[rB] + sRedS[128 + rB];
        mrow[0] = mnA;
        mrow[1] = mnB;
        #pragma unroll
        for (int n = 0; n < 8; n++) {
            ofr[n][0] *= alA; ofr[n][1] *= alA;
            ofr[n][2] *= alB; ofr[n][3] *= alB;
        }

        // --- O += P @ V (tf32): rows m0..+15, d-cols wc*64..+63
        const uint32_t* sPu = (const uint32_t*)sP;
        const uint32_t* sVu = smw + F4_V;
        #pragma unroll
        for (int ks2 = 0; ks2 < 8; ks2++) {
            const int k0 = ks2 * 8;
            uint32_t af[4];
            af[0] = sPu[rA * 68 + k0 + lc];
            af[1] = sPu[rB * 68 + k0 + lc];
            af[2] = sPu[rA * 68 + k0 + lc + 4];
            af[3] = sPu[rB * 68 + k0 + lc + 4];
            #pragma unroll
            for (int ni = 0; ni < 8; ni++) {
                const int d = wc * 64 + ni * 8 + lg;
                uint32_t b0 = sVu[(k0 + lc) * 132 + d];
                uint32_t b1 = sVu[(k0 + 4 + lc) * 132 + d];
                mma_m16n8k8(ofr[ni], af, b0, b1);
            }
        }
    }

    // --- write out (tf32-pre-rounded): O rows / l ---
    const float invA = 1.f / lrow[0];
    const float invB = 1.f / lrow[1];
    float* og = O + (size_t)(b * Ss + q0) * Dd + h * HDim;
    #pragma unroll
    for (int ni = 0; ni < 8; ni++) {
        const int col = wc * 64 + ni * 8 + 2 * lc;
        float2 oA, oB;
        oA.x = rna_tf32f(ofr[ni][0] * invA);
        oA.y = rna_tf32f(ofr[ni][1] * invA);
        oB.x = rna_tf32f(ofr[ni][2] * invB);
        oB.y = rna_tf32f(ofr[ni][3] * invB);
        *(float2*)(og + (size_t)rA * Dd + col) = oA;
        *(float2*)(og + (size_t)rB * Dd + col) = oB;
    }
}

// ---------------------------------------------------------------------------
extern "C" void kernel_launch(void* const* d_in, const int* in_sizes, int n_in,
                              void* d_out, int out_size)
{
    const float* subj = (const float*)d_in[0];
    const float* obj  = (const float*)d_in[1];
    const float* wq   = (const float*)d_in[2];
    const float* bq   = (const float*)d_in[3];
    const float* wk   = (const float*)d_in[4];
    const float* bk   = (const float*)d_in[5];
    const float* wv   = (const float*)d_in[6];
    const float* bv   = (const float*)d_in[7];
    const float* wc   = (const float*)d_in[8];
    const float* bc   = (const float*)d_in[9];
    const float* base = (const float*)d_in[10];
    float* out = (float*)d_out;

    float *Q, *K, *V, *C, *As, *Ao, *Wr;
    cudaGetSymbolAddress((void**)&Q, g_Q);
    cudaGetSymbolAddress((void**)&K, g_K);
    cudaGetSymbolAddress((void**)&V, g_V);
    cudaGetSymbolAddress((void**)&C, g_C);
    cudaGetSymbolAddress((void**)&As, g_As);
    cudaGetSymbolAddress((void**)&Ao, g_Ao);
    cudaGetSymbolAddress((void**)&Wr, g_Wr);
    const size_t WSZ = (size_t)Dd * Dd;

    cudaFuncSetAttribute(gemm_tc_kernel,
                         cudaFuncAttributeMaxDynamicSharedMemorySize, GEMM_SMEM);
    cudaFuncSetAttribute(flash4_kernel,
                         cudaFuncAttributeMaxDynamicSharedMemorySize, FLASH4_SMEM);

    rope_table2_kernel<<<(64 * Ss + 255) / 256, 256>>>(base);

    const int nA4 = (int)((size_t)MROWS * Dd / 4);
    const int nW4 = (int)(WSZ / 4);
    round_tf32_kernel<<<(nA4 + 255) / 256, 256>>>(subj, As, nA4);
    round_tf32_kernel<<<(nA4 + 255) / 256, 256>>>(obj,  Ao, nA4);
    round_tf32_kernel<<<(nW4 + 255) / 256, 256>>>(wq, Wr + 0 * WSZ, nW4);
    round_tf32_kernel<<<(nW4 + 255) / 256, 256>>>(wk, Wr + 1 * WSZ, nW4);
    round_tf32_kernel<<<(nW4 + 255) / 256, 256>>>(wv, Wr + 2 * WSZ, nW4);
    round_tf32_kernel<<<(nW4 + 255) / 256, 256>>>(wc, Wr + 3 * WSZ, nW4);

    dim3 gg(Dd / 128, MROWS / 128);
    gemm_tc_kernel<<<gg, 128, GEMM_SMEM>>>(As, Wr + 0 * WSZ, bq, Q, 1);
    gemm_tc_kernel<<<gg, 128, GEMM_SMEM>>>(Ao, Wr + 1 * WSZ, bk, K, 1);
    gemm_tc_kernel<<<gg, 128, GEMM_SMEM>>>(Ao, Wr + 2 * WSZ, bv, V, 0);

    flash4_kernel<<<dim3(Ss / 128, Hh, Bb), 512, FLASH4_SMEM>>>(Q, K, V, C);

    gemm_tc_kernel<<<gg, 128, GEMM_SMEM>>>(C, Wr + 3 * WSZ, bc, out, 0);
}

// round 14
// speedup vs baseline: 1.1524x; 1.0011x over previous
#include <cuda_runtime.h>
#include <cuda_bf16.h>
#include <math.h>
#include <stdint.h>

#define Bb 4
#define Ss 2048
#define Dd 2048
#define Hh 16
#define HDim 128
#define MROWS (Bb * Ss)  // 8192

// Scratch (allocation-free: device globals)
__device__ float g_Q[(size_t)Bb * Ss * Dd];
__device__ float g_K[(size_t)Bb * Ss * Dd];
__device__ float g_V[(size_t)Bb * Ss * Dd];
__device__ float g_C[(size_t)Bb * Ss * Dd];
__device__ float g_As[(size_t)MROWS * Dd];      // subj rounded to tf32
__device__ float g_Ao[(size_t)MROWS * Dd];      // obj rounded to tf32
__device__ float g_Wr[4][(size_t)Dd * Dd];      // weights rounded to tf32
__device__ float2 g_tab2[64 * Ss];              // [j][s] -> (cos, sin)

// ---------------------------------------------------------------------------
// helpers
// ---------------------------------------------------------------------------
__device__ __forceinline__ uint32_t smem_u32(const void* p) {
    uint32_t r;
    asm("{ .reg .u64 t; cvta.to.shared.u64 t, %1; cvt.u32.u64 %0, t; }"
        : "=r"(r) : "l"(p));
    return r;
}

#define CP_ASYNC16(smem, gptr) \
    asm volatile("cp.async.cg.shared.global [%0], [%1], 16;" \
                 :: "r"(smem), "l"(gptr) : "memory")
#define CP_COMMIT() asm volatile("cp.async.commit_group;" ::: "memory")
#define CP_WAIT(n)  asm volatile("cp.async.wait_group %0;" :: "n"(n) : "memory")

__device__ __forceinline__ uint32_t cvt_tf32(float x) {
    uint32_t r;
    asm("cvt.rna.tf32.f32 %0, %1;" : "=r"(r) : "f"(x));
    return r;
}
__device__ __forceinline__ float rna_tf32f(float x) {
    return __uint_as_float(cvt_tf32(x));
}

__device__ __forceinline__ void mma_m16n8k8(float* d, const uint32_t* a,
                                            uint32_t b0, uint32_t b1) {
    asm volatile(
        "mma.sync.aligned.m16n8k8.row.col.f32.tf32.tf32.f32 "
        "{%0,%1,%2,%3}, {%4,%5,%6,%7}, {%8,%9}, {%0,%1,%2,%3};"
        : "+f"(d[0]), "+f"(d[1]), "+f"(d[2]), "+f"(d[3])
        : "r"(a[0]), "r"(a[1]), "r"(a[2]), "r"(a[3]), "r"(b0), "r"(b1));
}

__device__ __forceinline__ void mma_bf16(float* d, const uint32_t* a,
                                         uint32_t b0, uint32_t b1) {
    asm volatile(
        "mma.sync.aligned.m16n8k16.row.col.f32.bf16.bf16.f32 "
        "{%0,%1,%2,%3}, {%4,%5,%6,%7}, {%8,%9}, {%0,%1,%2,%3};"
        : "+f"(d[0]), "+f"(d[1]), "+f"(d[2]), "+f"(d[3])
        : "r"(a[0]), "r"(a[1]), "r"(a[2]), "r"(a[3]), "r"(b0), "r"(b1));
}

// split (x,y) into packed bf16 hi pair + lo pair (x in low half)
__device__ __forceinline__ void split2(float x, float y,
                                       uint32_t& hi, uint32_t& lo) {
    __nv_bfloat162 h2 = __floats2bfloat162_rn(x, y);
    float hx = __bfloat162float(h2.x);
    float hy = __bfloat162float(h2.y);
    __nv_bfloat162 l2 = __floats2bfloat162_rn(x - hx, y - hy);
    hi = *reinterpret_cast<uint32_t*>(&h2);
    lo = *reinterpret_cast<uint32_t*>(&l2);
}

// ---------------------------------------------------------------------------
// Pre-round fp32 -> tf32-exact fp32 (RNA), merged variants.
// ---------------------------------------------------------------------------
__global__ __launch_bounds__(256) void round2_kernel(
    const float* __restrict__ s0, float* __restrict__ d0,
    const float* __restrict__ s1, float* __restrict__ d1, int n4)
{
    int i = blockIdx.x * blockDim.x + threadIdx.x;
    if (i >= n4) return;
    const float* src = blockIdx.y ? s1 : s0;
    float* dst = blockIdx.y ? d1 : d0;
    float4 v = ((const float4*)src)[i];
    uint4 o;
    o.x = cvt_tf32(v.x); o.y = cvt_tf32(v.y);
    o.z = cvt_tf32(v.z); o.w = cvt_tf32(v.w);
    ((uint4*)dst)[i] = o;
}

__global__ __launch_bounds__(256) void round4_kernel(
    const float* __restrict__ s0, const float* __restrict__ s1,
    const float* __restrict__ s2, const float* __restrict__ s3,
    float* __restrict__ dbase, int n4)
{
    int i = blockIdx.x * blockDim.x + threadIdx.x;
    if (i >= n4) return;
    const float* src = (blockIdx.y == 0) ? s0 : (blockIdx.y == 1) ? s1
                     : (blockIdx.y == 2) ? s2 : s3;
    float* dst = dbase + (size_t)blockIdx.y * Dd * Dd;
    float4 v = ((const float4*)src)[i];
    uint4 o;
    o.x = cvt_tf32(v.x); o.y = cvt_tf32(v.y);
    o.z = cvt_tf32(v.z); o.w = cvt_tf32(v.w);
    ((uint4*)dst)[i] = o;
}

// ---------------------------------------------------------------------------
// tf32 mma.sync GEMM on PRE-ROUNDED A and W.
// BM=BN=128, BK=32; 4 warps, warp tile 64x64; 3-stage cp.async,
// SINGLE barrier per mainloop iteration; 107.5KB smem -> 2 CTAs/SM.
// ---------------------------------------------------------------------------
#define BKt 32
#define NKT (Dd / BKt)            // 64
#define GST 3
#define SA_STRIDE 36
#define SB_STRIDE 136
#define SA_WORDS (128 * SA_STRIDE)   // 4608
#define SB_WORDS (BKt * SB_STRIDE)   // 4352
#define STAGE_WORDS (SA_WORDS + SB_WORDS)
#define GEMM_SMEM (GST * STAGE_WORDS * 4)  // 107520 B

__global__ __launch_bounds__(128, 2) void gemm_tc_kernel(
    const float* __restrict__ A, const float* __restrict__ W,
    const float* __restrict__ bias, float* __restrict__ C, int doRope)
{
    extern __shared__ float sm[];
    const int tid = threadIdx.x;
    const int wid = tid >> 5;
    const int lane = tid & 31;
    const int rowBase = blockIdx.y * 128;
    const int colBase = blockIdx.x * 128;

    const uint32_t sbase = smem_u32(sm);

    const float* aG = A + (size_t)(rowBase + (tid >> 3)) * Dd + (tid & 7) * 4;
    const float* bG = W + (size_t)(tid >> 5) * Dd + colBase + (tid & 31) * 4;
    const uint32_t aS = sbase + ((tid >> 3) * SA_STRIDE + (tid & 7) * 4) * 4;
    const uint32_t bS = sbase + (SA_WORDS + (tid >> 5) * SB_STRIDE + (tid & 31) * 4) * 4;

    const int wr = wid & 1;
    const int wc = wid >> 1;
    const int m0 = wr * 64;
    const int n0 = wc * 64;
    const int lg = lane >> 2;
    const int lc = lane & 3;

    float acc[4][8][4];
    #pragma unroll
    for (int mi = 0; mi < 4; mi++)
        #pragma unroll
        for (int ni = 0; ni < 8; ni++)
            #pragma unroll
            for (int r = 0; r < 4; r++) acc[mi][ni][r] = 0.f;

    // prologue: stages 0 and 1
    #pragma unroll
    for (int p = 0; p < 2; p++) {
        const float* ag = aG + p * BKt;
        const float* bg = bG + (size_t)p * BKt * Dd;
        const uint32_t as = aS + p * STAGE_WORDS * 4;
        const uint32_t bs = bS + p * STAGE_WORDS * 4;
        #pragma unroll
        for (int i = 0; i < 8; i++) {
            CP_ASYNC16(as + i * 16 * SA_STRIDE * 4, ag + (size_t)(16 * i) * Dd);
            CP_ASYNC16(bs + i * 4 * SB_STRIDE * 4,  bg + (size_t)(4 * i) * Dd);
        }
        CP_COMMIT();
    }

    int s = 0;
    for (int kt = 0; kt < NKT; kt++) {
        // stage s must be resident
        if (kt + 1 < NKT) { CP_WAIT(1); } else { CP_WAIT(0); }
        // one barrier: publishes stage s to all warps AND guarantees all
        // warps finished reading stage (s+2)%GST (read during kt-1) before
        // the prefetch below overwrites it.
        __syncthreads();

        if (kt + 2 < NKT) {
            int s2 = s + 2; if (s2 >= GST) s2 -= GST;
            const float* ag = aG + (kt + 2) * BKt;
            const float* bg = bG + (size_t)(kt + 2) * BKt * Dd;
            const uint32_t as = aS + s2 * STAGE_WORDS * 4;
            const uint32_t bs = bS + s2 * STAGE_WORDS * 4;
            #pragma unroll
            for (int i = 0; i < 8; i++) {
                CP_ASYNC16(as + i * 16 * SA_STRIDE * 4, ag + (size_t)(16 * i) * Dd);
                CP_ASYNC16(bs + i * 4 * SB_STRIDE * 4,  bg + (size_t)(4 * i) * Dd);
            }
            CP_COMMIT();
        }

        const uint32_t* sAp = (const uint32_t*)(sm + s * STAGE_WORDS);
        const uint32_t* sBp = sAp + SA_WORDS;

        #pragma unroll
        for (int ks = 0; ks < 4; ks++) {
            const int k0 = ks * 8;
            uint32_t afr[4][4];
            #pragma unroll
            for (int mi = 0; mi < 4; mi++) {
                const int r = m0 + mi * 16 + lg;
                const int c = k0 + lc;
                afr[mi][0] = sAp[r * SA_STRIDE + c];
                afr[mi][1] = sAp[(r + 8) * SA_STRIDE + c];
                afr[mi][2] = sAp[r * SA_STRIDE + c + 4];
                afr[mi][3] = sAp[(r + 8) * SA_STRIDE + c + 4];
            }
            #pragma unroll
            for (int ni = 0; ni < 8; ni++) {
                const int col = n0 + ni * 8 + lg;
                uint32_t b0 = sBp[(k0 + lc) * SB_STRIDE + col];
                uint32_t b1 = sBp[(k0 + 4 + lc) * SB_STRIDE + col];
                #pragma unroll
                for (int mi = 0; mi < 4; mi++)
                    mma_m16n8k8(acc[mi][ni], afr[mi], b0, b1);
            }
        }
        if (++s >= GST) s -= GST;
    }

    #pragma unroll
    for (int mi = 0; mi < 4; mi++) {
        const int row = rowBase + m0 + mi * 16 + lg;
        #pragma unroll
        for (int ni = 0; ni < 8; ni++) {
            const int col = colBase + n0 + ni * 8 + 2 * lc;
            const float bv0 = __ldg(bias + col);
            const float bv1 = __ldg(bias + col + 1);
            const int jn = (col & 127) >> 1;

            #pragma unroll
            for (int half = 0; half < 2; half++) {
                const int r = row + half * 8;
                float x0 = acc[mi][ni][2 * half]     + bv0;
                float x1 = acc[mi][ni][2 * half + 1] + bv1;
                if (doRope) {
                    float2 cs = g_tab2[jn * Ss + (r & (Ss - 1))];
                    float y0 = x0 * cs.x - x1 * cs.y;
                    float y1 = x0 * cs.y + x1 * cs.x;
                    x0 = y0; x1 = y1;
                }
                *(float2*)(C + (size_t)r * Dd + col) = make_float2(x0, x1);
            }
        }
    }
}

// ---------------------------------------------------------------------------
// RoPE cos/sin table (fp64 for angle accuracy), layout [j][s]
// ---------------------------------------------------------------------------
__global__ void rope_table2_kernel(const float* __restrict__ base_p)
{
    int t = blockIdx.x * blockDim.x + threadIdx.x;
    if (t >= 64 * Ss) return;
    int j = t >> 11, s = t & (Ss - 1);
    double base = (double)(*base_p);
    double f = exp(-(double)j / 64.0 * log(base));
    double ang = (double)s * f;
    double sn, cs;
    sincos(ang, &sn, &cs);
    g_tab2[t] = make_float2((float)cs, (float)sn);
}

// ---------------------------------------------------------------------------
// Flash attention v4 (unchanged from R13): QK bf16 hi/lo 3-term; PV tf32.
// CTA: 128-row Q tile, 512 threads (16 warps), 64-key tiles.
// ---------------------------------------------------------------------------
#define F4_QHI 0
#define F4_QLO (F4_QHI + 128 * 68)
#define F4_KHI (F4_QLO + 128 * 68)
#define F4_KLO (F4_KHI + 64 * 68)
#define F4_V   (F4_KLO + 64 * 68)     // V[t][d] tf32 fp32, stride 132
#define F4_P   (F4_V + 64 * 132)      // P[row][t] tf32 fp32, stride 68
#define F4_RM  (F4_P + 128 * 68)
#define F4_RS  (F4_RM + 256)
#define F4_WORDS (F4_RS + 256)
#define FLASH4_SMEM (F4_WORDS * 4)    // 175104 B

__global__ __launch_bounds__(512, 1) void flash4_kernel(
    const float* __restrict__ Q, const float* __restrict__ K,
    const float* __restrict__ V, float* __restrict__ O)
{
    extern __shared__ uint32_t smw[];
    float* sRedM = (float*)(smw + F4_RM);
    float* sRedS = (float*)(smw + F4_RS);
    float* sP = (float*)(smw + F4_P);

    const int qt = (Ss / 128 - 1) - blockIdx.x;   // big CTAs first
    const int h = blockIdx.y, b = blockIdx.z;
    const int tid = threadIdx.x;
    const int w = tid >> 5, lane = tid & 31;
    const int lg = lane >> 2, lc = lane & 3;
    const int wr = w & 7, wc = w >> 3;
    const int m0 = wr * 16;
    const int q0 = qt * 128;
    const float scale = 0.08838834764831845f;   // 1/sqrt(128), folded into Q

    const int rA = m0 + lg;
    const int rB = m0 + lg + 8;
    const int gRA = q0 + rA;
    const int gRB = q0 + rB;

    {
        const int row = tid >> 2;
        const float* qg = Q + (size_t)(b * Ss + q0 + row) * Dd + h * HDim;
        #pragma unroll
        for (int i = 0; i < 8; i++) {
            const int c4 = (tid & 3) + 4 * i;
            float4 v = *(const float4*)(qg + c4 * 4);
            v.x *= scale; v.y *= scale; v.z *= scale; v.w *= scale;
            uint32_t h0, l0, h1, l1;
            split2(v.x, v.y, h0, l0);
            split2(v.z, v.w, h1, l1);
            const int dp = c4 * 2;
            smw[F4_QHI + row * 68 + dp]     = h0;
            smw[F4_QHI + row * 68 + dp + 1] = h1;
            smw[F4_QLO + row * 68 + dp]     = l0;
            smw[F4_QLO + row * 68 + dp + 1] = l1;
        }
    }

    float mrow[2] = {-1e30f, -1e30f};
    float lrow[2] = {0.f, 0.f};
    float ofr[8][4];
    #pragma unroll
    for (int n = 0; n < 8; n++)
        #pragma unroll
        for (int r = 0; r < 4; r++) ofr[n][r] = 0.f;

    const int ktEnd = 2 * qt + 1;
    for (int kt = 0; kt <= ktEnd; kt++) {
        __syncthreads();

        {
            const int row = tid >> 3;
            const float* kg = K + (size_t)(b * Ss + kt * 64 + row) * Dd + h * HDim;
            #pragma unroll
            for (int i = 0; i < 4; i++) {
                const int c4 = (tid & 7) + 8 * i;
                float4 v = *(const float4*)(kg + c4 * 4);
                uint32_t h0, l0, h1, l1;
                split2(v.x, v.y, h0, l0);
                split2(v.z, v.w, h1, l1);
                const int dp = c4 * 2;
                smw[F4_KHI + row * 68 + dp]     = h0;
                smw[F4_KHI + row * 68 + dp + 1] = h1;
                smw[F4_KLO + row * 68 + dp]     = l0;
                smw[F4_KLO + row * 68 + dp + 1] = l1;
            }
        }
        {
            const int f4 = tid & 31;
            const int r0v = tid >> 5;
            const float* vg = V + (size_t)(b * Ss + kt * 64) * Dd + h * HDim;
            #pragma unroll
            for (int i = 0; i < 4; i++) {
                const int row = r0v + 16 * i;
                float4 v = *(const float4*)(vg + (size_t)row * Dd + f4 * 4);
                uint4 o;
                o.x = cvt_tf32(v.x);
                o.y = cvt_tf32(v.y);
                o.z = cvt_tf32(v.z);
                o.w = cvt_tf32(v.w);
                *(uint4*)&smw[F4_V + row * 132 + f4 * 4] = o;
            }
        }
        __syncthreads();

        float sfr[4][4];
        #pragma unroll
        for (int n = 0; n < 4; n++)
            #pragma unroll
            for (int r = 0; r < 4; r++) sfr[n][r] = 0.f;

        #pragma unroll
        for (int ks = 0; ks < 8; ks++) {
            const int kp = ks * 8;
            uint32_t ah[4], al[4];
            ah[0] = smw[F4_QHI + rA * 68 + kp + lc];
            ah[1] = smw[F4_QHI + rB * 68 + kp + lc];
            ah[2] = smw[F4_QHI + rA * 68 + kp + lc + 4];
            ah[3] = smw[F4_QHI + rB * 68 + kp + lc + 4];
            al[0] = smw[F4_QLO + rA * 68 + kp + lc];
            al[1] = smw[F4_QLO + rB * 68 + kp + lc];
            al[2] = smw[F4_QLO + rA * 68 + kp + lc + 4];
            al[3] = smw[F4_QLO + rB * 68 + kp + lc + 4];
            #pragma unroll
            for (int ni = 0; ni < 4; ni++) {
                const int j = wc * 32 + ni * 8 + lg;
                uint32_t bh0 = smw[F4_KHI + j * 68 + kp + lc];
                uint32_t bh1 = smw[F4_KHI + j * 68 + kp + lc + 4];
                uint32_t bl0 = smw[F4_KLO + j * 68 + kp + lc];
                uint32_t bl1 = smw[F4_KLO + j * 68 + kp + lc + 4];
                mma_bf16(sfr[ni], ah, bh0, bh1);
                mma_bf16(sfr[ni], ah, bl0, bl1);
                mma_bf16(sfr[ni], al, bh0, bh1);
            }
        }

        const bool diag = (kt >= 2 * qt);
        float vA = -1e30f, vB = -1e30f;
        #pragma unroll
        for (int ni = 0; ni < 4; ni++) {
            if (diag) {
                const int gc0 = kt * 64 + wc * 32 + ni * 8 + 2 * lc;
                if (gc0 > gRA)     sfr[ni][0] = -1e30f;
                if (gc0 + 1 > gRA) sfr[ni][1] = -1e30f;
                if (gc0 > gRB)     sfr[ni][2] = -1e30f;
                if (gc0 + 1 > gRB) sfr[ni][3] = -1e30f;
            }
            vA = fmaxf(vA, fmaxf(sfr[ni][0], sfr[ni][1]));
            vB = fmaxf(vB, fmaxf(sfr[ni][2], sfr[ni][3]));
        }
        vA = fmaxf(vA, __shfl_xor_sync(0xffffffffu, vA, 1));
        vA = fmaxf(vA, __shfl_xor_sync(0xffffffffu, vA, 2));
        vB = fmaxf(vB, __shfl_xor_sync(0xffffffffu, vB, 1));
        vB = fmaxf(vB, __shfl_xor_sync(0xffffffffu, vB, 2));
        if (lc == 0) {
            sRedM[wc * 128 + rA] = vA;
            sRedM[wc * 128 + rB] = vB;
        }
        __syncthreads();
        const float mtA = fmaxf(sRedM[rA], sRedM[128 + rA]);
        const float mtB = fmaxf(sRedM[rB], sRedM[128 + rB]);
        const float mnA = fmaxf(mrow[0], mtA);
        const float mnB = fmaxf(mrow[1], mtB);
        const float alA = __expf(mrow[0] - mnA);
        const float alB = __expf(mrow[1] - mnB);

        float sumA = 0.f, sumB = 0.f;
        #pragma unroll
        for (int ni = 0; ni < 4; ni++) {
            float p0 = rna_tf32f(__expf(sfr[ni][0] - mnA));
            float p1 = rna_tf32f(__expf(sfr[ni][1] - mnA));
            float p2 = rna_tf32f(__expf(sfr[ni][2] - mnB));
            float p3 = rna_tf32f(__expf(sfr[ni][3] - mnB));
            sumA += p0 + p1;
            sumB += p2 + p3;
            const int t0 = wc * 32 + ni * 8 + 2 * lc;
            *(float2*)&sP[rA * 68 + t0] = make_float2(p0, p1);
            *(float2*)&sP[rB * 68 + t0] = make_float2(p2, p3);
        }
        sumA += __shfl_xor_sync(0xffffffffu, sumA, 1);
        sumA += __shfl_xor_sync(0xffffffffu, sumA, 2);
        sumB += __shfl_xor_sync(0xffffffffu, sumB, 1);
        sumB += __shfl_xor_sync(0xffffffffu, sumB, 2);
        if (lc == 0) {
            sRedS[wc * 128 + rA] = sumA;
            sRedS[wc * 128 + rB] = sumB;
        }
        __syncthreads();
        lrow[0] = lrow[0] * alA + sRedS[rA] + sRedS[128 + rA];
        lrow[1] = lrow[1] * alB + sRedS[rB] + sRedS[128 + rB];
        mrow[0] = mnA;
        mrow[1] = mnB;
        #pragma unroll
        for (int n = 0; n < 8; n++) {
            ofr[n][0] *= alA; ofr[n][1] *= alA;
            ofr[n][2] *= alB; ofr[n][3] *= alB;
        }

        const uint32_t* sPu = (const uint32_t*)sP;
        const uint32_t* sVu = smw + F4_V;
        #pragma unroll
        for (int ks2 = 0; ks2 < 8; ks2++) {
            const int k0 = ks2 * 8;
            uint32_t af[4];
            af[0] = sPu[rA * 68 + k0 + lc];
            af[1] = sPu[rB * 68 + k0 + lc];
            af[2] = sPu[rA * 68 + k0 + lc + 4];
            af[3] = sPu[rB * 68 + k0 + lc + 4];
            #pragma unroll
            for (int ni = 0; ni < 8; ni++) {
                const int d = wc * 64 + ni * 8 + lg;
                uint32_t b0 = sVu[(k0 + lc) * 132 + d];
                uint32_t b1 = sVu[(k0 + 4 + lc) * 132 + d];
                mma_m16n8k8(ofr[ni], af, b0, b1);
            }
        }
    }

    const float invA = 1.f / lrow[0];
    const float invB = 1.f / lrow[1];
    float* og = O + (size_t)(b * Ss + q0) * Dd + h * HDim;
    #pragma unroll
    for (int ni = 0; ni < 8; ni++) {
        const int col = wc * 64 + ni * 8 + 2 * lc;
        float2 oA, oB;
        oA.x = rna_tf32f(ofr[ni][0] * invA);
        oA.y = rna_tf32f(ofr[ni][1] * invA);
        oB.x = rna_tf32f(ofr[ni][2] * invB);
        oB.y = rna_tf32f(ofr[ni][3] * invB);
        *(float2*)(og + (size_t)rA * Dd + col) = oA;
        *(float2*)(og + (size_t)rB * Dd + col) = oB;
    }
}

// ---------------------------------------------------------------------------
extern "C" void kernel_launch(void* const* d_in, const int* in_sizes, int n_in,
                              void* d_out, int out_size)
{
    const float* subj = (const float*)d_in[0];
    const float* obj  = (const float*)d_in[1];
    const float* wq   = (const float*)d_in[2];
    const float* bq   = (const float*)d_in[3];
    const float* wk   = (const float*)d_in[4];
    const float* bk   = (const float*)d_in[5];
    const float* wv   = (const float*)d_in[6];
    const float* bv   = (const float*)d_in[7];
    const float* wc   = (const float*)d_in[8];
    const float* bc   = (const float*)d_in[9];
    const float* base = (const float*)d_in[10];
    float* out = (float*)d_out;

    float *Q, *K, *V, *C, *As, *Ao, *Wr;
    cudaGetSymbolAddress((void**)&Q, g_Q);
    cudaGetSymbolAddress((void**)&K, g_K);
    cudaGetSymbolAddress((void**)&V, g_V);
    cudaGetSymbolAddress((void**)&C, g_C);
    cudaGetSymbolAddress((void**)&As, g_As);
    cudaGetSymbolAddress((void**)&Ao, g_Ao);
    cudaGetSymbolAddress((void**)&Wr, g_Wr);
    const size_t WSZ = (size_t)Dd * Dd;

    cudaFuncSetAttribute(gemm_tc_kernel,
                         cudaFuncAttributeMaxDynamicSharedMemorySize, GEMM_SMEM);
    cudaFuncSetAttribute(flash4_kernel,
                         cudaFuncAttributeMaxDynamicSharedMemorySize, FLASH4_SMEM);

    // launch order: table(1), round2(2), round4(3), gemmQ(4), gemmK(5),
    // gemmV(6) <- ncu (-s 5 -c 1) captures gemmV
    rope_table2_kernel<<<(64 * Ss + 255) / 256, 256>>>(base);

    const int nA4 = (int)((size_t)MROWS * Dd / 4);
    const int nW4 = (int)(WSZ / 4);
    round2_kernel<<<dim3((nA4 + 255) / 256, 2), 256>>>(subj, As, obj, Ao, nA4);
    round4_kernel<<<dim3((nW4 + 255) / 256, 4), 256>>>(wq, wk, wv, wc, Wr, nW4);

    dim3 gg(Dd / 128, MROWS / 128);
    gemm_tc_kernel<<<gg, 128, GEMM_SMEM>>>(As, Wr + 0 * WSZ, bq, Q, 1);
    gemm_tc_kernel<<<gg, 128, GEMM_SMEM>>>(Ao, Wr + 1 * WSZ, bk, K, 1);
    gemm_tc_kernel<<<gg, 128, GEMM_SMEM>>>(Ao, Wr + 2 * WSZ, bv, V, 0);

    flash4_kernel<<<dim3(Ss / 128, Hh, Bb), 512, FLASH4_SMEM>>>(Q, K, V, C);

    gemm_tc_kernel<<<gg, 128, GEMM_SMEM>>>(C, Wr + 3 * WSZ, bc, out, 0);
}

// round 15
// speedup vs baseline: 1.1943x; 1.0364x over previous
#include <cuda_runtime.h>
#include <cuda_bf16.h>
#include <math.h>
#include <stdint.h>

#define Bb 4
#define Ss 2048
#define Dd 2048
#define Hh 16
#define HDim 128
#define MROWS (Bb * Ss)  // 8192

// Scratch (allocation-free: device globals)
__device__ float g_Q[(size_t)Bb * Ss * Dd];
__device__ float g_K[(size_t)Bb * Ss * Dd];
__device__ float g_V[(size_t)Bb * Ss * Dd];
__device__ float g_C[(size_t)Bb * Ss * Dd];
__device__ float g_As[(size_t)MROWS * Dd];      // subj rounded to tf32
__device__ float g_Ao[(size_t)MROWS * Dd];      // obj rounded to tf32
__device__ float g_Wr[4][(size_t)Dd * Dd];      // weights rounded to tf32
__device__ float2 g_tab2[64 * Ss];              // [j][s] -> (cos, sin)

// ---------------------------------------------------------------------------
// helpers
// ---------------------------------------------------------------------------
__device__ __forceinline__ uint32_t smem_u32(const void* p) {
    uint32_t r;
    asm("{ .reg .u64 t; cvta.to.shared.u64 t, %1; cvt.u32.u64 %0, t; }"
        : "=r"(r) : "l"(p));
    return r;
}

#define CP_ASYNC16(smem, gptr) \
    asm volatile("cp.async.cg.shared.global [%0], [%1], 16;" \
                 :: "r"(smem), "l"(gptr) : "memory")
#define CP_COMMIT() asm volatile("cp.async.commit_group;" ::: "memory")
#define CP_WAIT(n)  asm volatile("cp.async.wait_group %0;" :: "n"(n) : "memory")

__device__ __forceinline__ uint32_t cvt_tf32(float x) {
    uint32_t r;
    asm("cvt.rna.tf32.f32 %0, %1;" : "=r"(r) : "f"(x));
    return r;
}
__device__ __forceinline__ float rna_tf32f(float x) {
    return __uint_as_float(cvt_tf32(x));
}

__device__ __forceinline__ void mma_m16n8k8(float* d, const uint32_t* a,
                                            uint32_t b0, uint32_t b1) {
    asm volatile(
        "mma.sync.aligned.m16n8k8.row.col.f32.tf32.tf32.f32 "
        "{%0,%1,%2,%3}, {%4,%5,%6,%7}, {%8,%9}, {%0,%1,%2,%3};"
        : "+f"(d[0]), "+f"(d[1]), "+f"(d[2]), "+f"(d[3])
        : "r"(a[0]), "r"(a[1]), "r"(a[2]), "r"(a[3]), "r"(b0), "r"(b1));
}

__device__ __forceinline__ void mma_bf16(float* d, const uint32_t* a,
                                         uint32_t b0, uint32_t b1) {
    asm volatile(
        "mma.sync.aligned.m16n8k16.row.col.f32.bf16.bf16.f32 "
        "{%0,%1,%2,%3}, {%4,%5,%6,%7}, {%8,%9}, {%0,%1,%2,%3};"
        : "+f"(d[0]), "+f"(d[1]), "+f"(d[2]), "+f"(d[3])
        : "r"(a[0]), "r"(a[1]), "r"(a[2]), "r"(a[3]), "r"(b0), "r"(b1));
}

// split (x,y) into packed bf16 hi pair + lo pair (x in low half)
__device__ __forceinline__ void split2(float x, float y,
                                       uint32_t& hi, uint32_t& lo) {
    __nv_bfloat162 h2 = __floats2bfloat162_rn(x, y);
    float hx = __bfloat162float(h2.x);
    float hy = __bfloat162float(h2.y);
    __nv_bfloat162 l2 = __floats2bfloat162_rn(x - hx, y - hy);
    hi = *reinterpret_cast<uint32_t*>(&h2);
    lo = *reinterpret_cast<uint32_t*>(&l2);
}

// ---------------------------------------------------------------------------
// Pre-round fp32 -> tf32-exact fp32 (RNA).
// ---------------------------------------------------------------------------
__global__ __launch_bounds__(256) void round_tf32_kernel(
    const float* __restrict__ src, float* __restrict__ dst, int n4)
{
    int i = blockIdx.x * blockDim.x + threadIdx.x;
    if (i >= n4) return;
    float4 v = ((const float4*)src)[i];
    uint4 o;
    o.x = cvt_tf32(v.x); o.y = cvt_tf32(v.y);
    o.z = cvt_tf32(v.z); o.w = cvt_tf32(v.w);
    ((uint4*)dst)[i] = o;
}

__global__ __launch_bounds__(256) void round4_kernel(
    const float* __restrict__ s0, const float* __restrict__ s1,
    const float* __restrict__ s2, const float* __restrict__ s3,
    float* __restrict__ dbase, int n4)
{
    int i = blockIdx.x * blockDim.x + threadIdx.x;
    if (i >= n4) return;
    const float* src = (blockIdx.y == 0) ? s0 : (blockIdx.y == 1) ? s1
                     : (blockIdx.y == 2) ? s2 : s3;
    float* dst = dbase + (size_t)blockIdx.y * Dd * Dd;
    float4 v = ((const float4*)src)[i];
    uint4 o;
    o.x = cvt_tf32(v.x); o.y = cvt_tf32(v.y);
    o.z = cvt_tf32(v.z); o.w = cvt_tf32(v.w);
    ((uint4*)dst)[i] = o;
}

// ---------------------------------------------------------------------------
// tf32 mma.sync GEMM core (R14 config: 4 warps, 64x64 warp tile, 3-stage,
// single barrier, 2 CTAs/SM).
// ---------------------------------------------------------------------------
#define BKt 32
#define NKT (Dd / BKt)            // 64
#define GST 3
#define SA_STRIDE 36
#define SB_STRIDE 136
#define SA_WORDS (128 * SA_STRIDE)   // 4608
#define SB_WORDS (BKt * SB_STRIDE)   // 4352
#define STAGE_WORDS (SA_WORDS + SB_WORDS)
#define GEMM_SMEM (GST * STAGE_WORDS * 4)  // 107520 B

__device__ __forceinline__ void gemm_core(
    float* sm,
    const float* __restrict__ A, const float* __restrict__ W,
    const float* __restrict__ bias, float* __restrict__ C, int doRope)
{
    const int tid = threadIdx.x;
    const int wid = tid >> 5;
    const int lane = tid & 31;
    const int rowBase = blockIdx.y * 128;
    const int colBase = blockIdx.x * 128;

    const uint32_t sbase = smem_u32(sm);

    const float* aG = A + (size_t)(rowBase + (tid >> 3)) * Dd + (tid & 7) * 4;
    const float* bG = W + (size_t)(tid >> 5) * Dd + colBase + (tid & 31) * 4;
    const uint32_t aS = sbase + ((tid >> 3) * SA_STRIDE + (tid & 7) * 4) * 4;
    const uint32_t bS = sbase + (SA_WORDS + (tid >> 5) * SB_STRIDE + (tid & 31) * 4) * 4;

    const int wr = wid & 1;
    const int wc = wid >> 1;
    const int m0 = wr * 64;
    const int n0 = wc * 64;
    const int lg = lane >> 2;
    const int lc = lane & 3;

    float acc[4][8][4];
    #pragma unroll
    for (int mi = 0; mi < 4; mi++)
        #pragma unroll
        for (int ni = 0; ni < 8; ni++)
            #pragma unroll
            for (int r = 0; r < 4; r++) acc[mi][ni][r] = 0.f;

    #pragma unroll
    for (int p = 0; p < 2; p++) {
        const float* ag = aG + p * BKt;
        const float* bg = bG + (size_t)p * BKt * Dd;
        const uint32_t as = aS + p * STAGE_WORDS * 4;
        const uint32_t bs = bS + p * STAGE_WORDS * 4;
        #pragma unroll
        for (int i = 0; i < 8; i++) {
            CP_ASYNC16(as + i * 16 * SA_STRIDE * 4, ag + (size_t)(16 * i) * Dd);
            CP_ASYNC16(bs + i * 4 * SB_STRIDE * 4,  bg + (size_t)(4 * i) * Dd);
        }
        CP_COMMIT();
    }

    int s = 0;
    for (int kt = 0; kt < NKT; kt++) {
        if (kt + 1 < NKT) { CP_WAIT(1); } else { CP_WAIT(0); }
        __syncthreads();

        if (kt + 2 < NKT) {
            int s2 = s + 2; if (s2 >= GST) s2 -= GST;
            const float* ag = aG + (kt + 2) * BKt;
            const float* bg = bG + (size_t)(kt + 2) * BKt * Dd;
            const uint32_t as = aS + s2 * STAGE_WORDS * 4;
            const uint32_t bs = bS + s2 * STAGE_WORDS * 4;
            #pragma unroll
            for (int i = 0; i < 8; i++) {
                CP_ASYNC16(as + i * 16 * SA_STRIDE * 4, ag + (size_t)(16 * i) * Dd);
                CP_ASYNC16(bs + i * 4 * SB_STRIDE * 4,  bg + (size_t)(4 * i) * Dd);
            }
            CP_COMMIT();
        }

        const uint32_t* sAp = (const uint32_t*)(sm + s * STAGE_WORDS);
        const uint32_t* sBp = sAp + SA_WORDS;

        #pragma unroll
        for (int ks = 0; ks < 4; ks++) {
            const int k0 = ks * 8;
            uint32_t afr[4][4];
            #pragma unroll
            for (int mi = 0; mi < 4; mi++) {
                const int r = m0 + mi * 16 + lg;
                const int c = k0 + lc;
                afr[mi][0] = sAp[r * SA_STRIDE + c];
                afr[mi][1] = sAp[(r + 8) * SA_STRIDE + c];
                afr[mi][2] = sAp[r * SA_STRIDE + c + 4];
                afr[mi][3] = sAp[(r + 8) * SA_STRIDE + c + 4];
            }
            #pragma unroll
            for (int ni = 0; ni < 8; ni++) {
                const int col = n0 + ni * 8 + lg;
                uint32_t b0 = sBp[(k0 + lc) * SB_STRIDE + col];
                uint32_t b1 = sBp[(k0 + 4 + lc) * SB_STRIDE + col];
                #pragma unroll
                for (int mi = 0; mi < 4; mi++)
                    mma_m16n8k8(acc[mi][ni], afr[mi], b0, b1);
            }
        }
        if (++s >= GST) s -= GST;
    }

    #pragma unroll
    for (int mi = 0; mi < 4; mi++) {
        const int row = rowBase + m0 + mi * 16 + lg;
        #pragma unroll
        for (int ni = 0; ni < 8; ni++) {
            const int col = colBase + n0 + ni * 8 + 2 * lc;
            const float bv0 = __ldg(bias + col);
            const float bv1 = __ldg(bias + col + 1);
            const int jn = (col & 127) >> 1;

            #pragma unroll
            for (int half = 0; half < 2; half++) {
                const int r = row + half * 8;
                float x0 = acc[mi][ni][2 * half]     + bv0;
                float x1 = acc[mi][ni][2 * half + 1] + bv1;
                if (doRope) {
                    float2 cs = g_tab2[jn * Ss + (r & (Ss - 1))];
                    float y0 = x0 * cs.x - x1 * cs.y;
                    float y1 = x0 * cs.y + x1 * cs.x;
                    x0 = y0; x1 = y1;
                }
                *(float2*)(C + (size_t)r * Dd + col) = make_float2(x0, x1);
            }
        }
    }
}

// merged Q/K/V projection: blockIdx.z selects operands
__global__ __launch_bounds__(128, 2) void gemm3_kernel(
    const float* __restrict__ As, const float* __restrict__ Ao,
    const float* __restrict__ Wr,
    const float* __restrict__ bq, const float* __restrict__ bk,
    const float* __restrict__ bv,
    float* __restrict__ Q, float* __restrict__ K, float* __restrict__ V)
{
    extern __shared__ float sm[];
    const int z = blockIdx.z;
    const float* A = (z == 0) ? As : Ao;
    const float* W = Wr + (size_t)z * Dd * Dd;
    const float* bias = (z == 0) ? bq : (z == 1) ? bk : bv;
    float* C = (z == 0) ? Q : (z == 1) ? K : V;
    gemm_core(sm, A, W, bias, C, (z < 2) ? 1 : 0);
}

__global__ __launch_bounds__(128, 2) void gemm_tc_kernel(
    const float* __restrict__ A, const float* __restrict__ W,
    const float* __restrict__ bias, float* __restrict__ C, int doRope)
{
    extern __shared__ float sm[];
    gemm_core(sm, A, W, bias, C, doRope);
}

// ---------------------------------------------------------------------------
// RoPE cos/sin table (fp64 for angle accuracy), layout [j][s]
// ---------------------------------------------------------------------------
__global__ void rope_table2_kernel(const float* __restrict__ base_p)
{
    int t = blockIdx.x * blockDim.x + threadIdx.x;
    if (t >= 64 * Ss) return;
    int j = t >> 11, s = t & (Ss - 1);
    double base = (double)(*base_p);
    double f = exp(-(double)j / 64.0 * log(base));
    double ang = (double)s * f;
    double sn, cs;
    sincos(ang, &sn, &cs);
    g_tab2[t] = make_float2((float)cs, (float)sn);
}

// ---------------------------------------------------------------------------
// Flash attention v5: flash4 math (QK bf16 hi/lo 3-term, PV tf32) with K/V
// GLOBAL loads software-pipelined through registers: tile kt+1's LDGs issue
// before tile kt's compute, hiding global latency behind ~5K cycles of MMA.
// ---------------------------------------------------------------------------
#define F4_QHI 0
#define F4_QLO (F4_QHI + 128 * 68)
#define F4_KHI (F4_QLO + 128 * 68)
#define F4_KLO (F4_KHI + 64 * 68)
#define F4_V   (F4_KLO + 64 * 68)     // V[t][d] tf32 fp32, stride 132
#define F4_P   (F4_V + 64 * 132)      // P[row][t] tf32 fp32, stride 68
#define F4_RM  (F4_P + 128 * 68)
#define F4_RS  (F4_RM + 256)
#define F4_WORDS (F4_RS + 256)
#define FLASH5_SMEM (F4_WORDS * 4)    // 175104 B

__global__ __launch_bounds__(512, 1) void flash5_kernel(
    const float* __restrict__ Q, const float* __restrict__ K,
    const float* __restrict__ V, float* __restrict__ O)
{
    extern __shared__ uint32_t smw[];
    float* sRedM = (float*)(smw + F4_RM);
    float* sRedS = (float*)(smw + F4_RS);
    float* sP = (float*)(smw + F4_P);

    const int qt = (Ss / 128 - 1) - blockIdx.x;   // big CTAs first
    const int h = blockIdx.y, b = blockIdx.z;
    const int tid = threadIdx.x;
    const int w = tid >> 5, lane = tid & 31;
    const int lg = lane >> 2, lc = lane & 3;
    const int wr = w & 7, wc = w >> 3;
    const int m0 = wr * 16;
    const int q0 = qt * 128;
    const float scale = 0.08838834764831845f;   // 1/sqrt(128), folded into Q

    const int rA = m0 + lg;
    const int rB = m0 + lg + 8;
    const int gRA = q0 + rA;
    const int gRB = q0 + rB;

    // K/V prefetch mappings (registers)
    const int krow = tid >> 3;                 // 0..63
    const int kc8 = tid & 7;
    const int vrow0 = tid >> 5;                // 0..15
    const int vf4 = tid & 31;
    const float* kgBase = K + (size_t)(b * Ss) * Dd + h * HDim;
    const float* vgBase = V + (size_t)(b * Ss) * Dd + h * HDim;

    float4 kreg[4], vreg[4];
    {   // prologue: tile 0 into registers
        const float* kg = kgBase + (size_t)krow * Dd;
        #pragma unroll
        for (int i = 0; i < 4; i++)
            kreg[i] = *(const float4*)(kg + (kc8 + 8 * i) * 4);
        #pragma unroll
        for (int i = 0; i < 4; i++)
            vreg[i] = *(const float4*)(vgBase + (size_t)(vrow0 + 16 * i) * Dd + vf4 * 4);
    }

    // --- load Q tile (128x128), scale + split to bf16 hi/lo pairs ---
    {
        const int row = tid >> 2;
        const float* qg = Q + (size_t)(b * Ss + q0 + row) * Dd + h * HDim;
        #pragma unroll
        for (int i = 0; i < 8; i++) {
            const int c4 = (tid & 3) + 4 * i;
            float4 v = *(const float4*)(qg + c4 * 4);
            v.x *= scale; v.y *= scale; v.z *= scale; v.w *= scale;
            uint32_t h0, l0, h1, l1;
            split2(v.x, v.y, h0, l0);
            split2(v.z, v.w, h1, l1);
            const int dp = c4 * 2;
            smw[F4_QHI + row * 68 + dp]     = h0;
            smw[F4_QHI + row * 68 + dp + 1] = h1;
            smw[F4_QLO + row * 68 + dp]     = l0;
            smw[F4_QLO + row * 68 + dp + 1] = l1;
        }
    }

    float mrow[2] = {-1e30f, -1e30f};
    float lrow[2] = {0.f, 0.f};
    float ofr[8][4];
    #pragma unroll
    for (int n = 0; n < 8; n++)
        #pragma unroll
        for (int r = 0; r < 4; r++) ofr[n][r] = 0.f;

    const int ktEnd = 2 * qt + 1;
    for (int kt = 0; kt <= ktEnd; kt++) {
        __syncthreads();   // prev iter reads of sK/sV/sP done; Q store done

        // --- store tile kt from registers: K split, V tf32 ---
        #pragma unroll
        for (int i = 0; i < 4; i++) {
            float4 v = kreg[i];
            uint32_t h0, l0, h1, l1;
            split2(v.x, v.y, h0, l0);
            split2(v.z, v.w, h1, l1);
            const int dp = (kc8 + 8 * i) * 2;
            smw[F4_KHI + krow * 68 + dp]     = h0;
            smw[F4_KHI + krow * 68 + dp + 1] = h1;
            smw[F4_KLO + krow * 68 + dp]     = l0;
            smw[F4_KLO + krow * 68 + dp + 1] = l1;
        }
        #pragma unroll
        for (int i = 0; i < 4; i++) {
            const int row = vrow0 + 16 * i;
            float4 v = vreg[i];
            uint4 o;
            o.x = cvt_tf32(v.x); o.y = cvt_tf32(v.y);
            o.z = cvt_tf32(v.z); o.w = cvt_tf32(v.w);
            *(uint4*)&smw[F4_V + row * 132 + vf4 * 4] = o;
        }
        __syncthreads();

        // --- prefetch tile kt+1 into registers (latency hidden by compute)
        if (kt < ktEnd) {
            const float* kg = kgBase + (size_t)((kt + 1) * 64 + krow) * Dd;
            #pragma unroll
            for (int i = 0; i < 4; i++)
                kreg[i] = *(const float4*)(kg + (kc8 + 8 * i) * 4);
            const float* vg = vgBase + (size_t)((kt + 1) * 64) * Dd;
            #pragma unroll
            for (int i = 0; i < 4; i++)
                vreg[i] = *(const float4*)(vg + (size_t)(vrow0 + 16 * i) * Dd + vf4 * 4);
        }

        // --- S = Q @ K^T (3-term bf16): rows m0..+15, cols wc*32..+31
        float sfr[4][4];
        #pragma unroll
        for (int n = 0; n < 4; n++)
            #pragma unroll
            for (int r = 0; r < 4; r++) sfr[n][r] = 0.f;

        #pragma unroll
        for (int ks = 0; ks < 8; ks++) {
            const int kp = ks * 8;
            uint32_t ah[4], al[4];
            ah[0] = smw[F4_QHI + rA * 68 + kp + lc];
            ah[1] = smw[F4_QHI + rB * 68 + kp + lc];
            ah[2] = smw[F4_QHI + rA * 68 + kp + lc + 4];
            ah[3] = smw[F4_QHI + rB * 68 + kp + lc + 4];
            al[0] = smw[F4_QLO + rA * 68 + kp + lc];
            al[1] = smw[F4_QLO + rB * 68 + kp + lc];
            al[2] = smw[F4_QLO + rA * 68 + kp + lc + 4];
            al[3] = smw[F4_QLO + rB * 68 + kp + lc + 4];
            #pragma unroll
            for (int ni = 0; ni < 4; ni++) {
                const int j = wc * 32 + ni * 8 + lg;
                uint32_t bh0 = smw[F4_KHI + j * 68 + kp + lc];
                uint32_t bh1 = smw[F4_KHI + j * 68 + kp + lc + 4];
                uint32_t bl0 = smw[F4_KLO + j * 68 + kp + lc];
                uint32_t bl1 = smw[F4_KLO + j * 68 + kp + lc + 4];
                mma_bf16(sfr[ni], ah, bh0, bh1);
                mma_bf16(sfr[ni], ah, bl0, bl1);
                mma_bf16(sfr[ni], al, bh0, bh1);
            }
        }

        // --- online softmax on C-fragments ---
        const bool diag = (kt >= 2 * qt);
        float vA = -1e30f, vB = -1e30f;
        #pragma unroll
        for (int ni = 0; ni < 4; ni++) {
            if (diag) {
                const int gc0 = kt * 64 + wc * 32 + ni * 8 + 2 * lc;
                if (gc0 > gRA)     sfr[ni][0] = -1e30f;
                if (gc0 + 1 > gRA) sfr[ni][1] = -1e30f;
                if (gc0 > gRB)     sfr[ni][2] = -1e30f;
                if (gc0 + 1 > gRB) sfr[ni][3] = -1e30f;
            }
            vA = fmaxf(vA, fmaxf(sfr[ni][0], sfr[ni][1]));
            vB = fmaxf(vB, fmaxf(sfr[ni][2], sfr[ni][3]));
        }
        vA = fmaxf(vA, __shfl_xor_sync(0xffffffffu, vA, 1));
        vA = fmaxf(vA, __shfl_xor_sync(0xffffffffu, vA, 2));
        vB = fmaxf(vB, __shfl_xor_sync(0xffffffffu, vB, 1));
        vB = fmaxf(vB, __shfl_xor_sync(0xffffffffu, vB, 2));
        if (lc == 0) {
            sRedM[wc * 128 + rA] = vA;
            sRedM[wc * 128 + rB] = vB;
        }
        __syncthreads();
        const float mtA = fmaxf(sRedM[rA], sRedM[128 + rA]);
        const float mtB = fmaxf(sRedM[rB], sRedM[128 + rB]);
        const float mnA = fmaxf(mrow[0], mtA);
        const float mnB = fmaxf(mrow[1], mtB);
        const float alA = __expf(mrow[0] - mnA);
        const float alB = __expf(mrow[1] - mnB);

        float sumA = 0.f, sumB = 0.f;
        #pragma unroll
        for (int ni = 0; ni < 4; ni++) {
            float p0 = rna_tf32f(__expf(sfr[ni][0] - mnA));
            float p1 = rna_tf32f(__expf(sfr[ni][1] - mnA));
            float p2 = rna_tf32f(__expf(sfr[ni][2] - mnB));
            float p3 = rna_tf32f(__expf(sfr[ni][3] - mnB));
            sumA += p0 + p1;
            sumB += p2 + p3;
            const int t0 = wc * 32 + ni * 8 + 2 * lc;
            *(float2*)&sP[rA * 68 + t0] = make_float2(p0, p1);
            *(float2*)&sP[rB * 68 + t0] = make_float2(p2, p3);
        }
        sumA += __shfl_xor_sync(0xffffffffu, sumA, 1);
        sumA += __shfl_xor_sync(0xffffffffu, sumA, 2);
        sumB += __shfl_xor_sync(0xffffffffu, sumB, 1);
        sumB += __shfl_xor_sync(0xffffffffu, sumB, 2);
        if (lc == 0) {
            sRedS[wc * 128 + rA] = sumA;
            sRedS[wc * 128 + rB] = sumB;
        }
        __syncthreads();   // also publishes P
        lrow[0] = lrow[0] * alA + sRedS[rA] + sRedS[128 + rA];
        lrow[1] = lrow[1] * alB + sRedS[rB] + sRedS[128 + rB];
        mrow[0] = mnA;
        mrow[1] = mnB;
        #pragma unroll
        for (int n = 0; n < 8; n++) {
            ofr[n][0] *= alA; ofr[n][1] *= alA;
            ofr[n][2] *= alB; ofr[n][3] *= alB;
        }

        // --- O += P @ V (tf32): rows m0..+15, d-cols wc*64..+63
        const uint32_t* sPu = (const uint32_t*)sP;
        const uint32_t* sVu = smw + F4_V;
        #pragma unroll
        for (int ks2 = 0; ks2 < 8; ks2++) {
            const int k0 = ks2 * 8;
            uint32_t af[4];
            af[0] = sPu[rA * 68 + k0 + lc];
            af[1] = sPu[rB * 68 + k0 + lc];
            af[2] = sPu[rA * 68 + k0 + lc + 4];
            af[3] = sPu[rB * 68 + k0 + lc + 4];
            #pragma unroll
            for (int ni = 0; ni < 8; ni++) {
                const int d = wc * 64 + ni * 8 + lg;
                uint32_t b0 = sVu[(k0 + lc) * 132 + d];
                uint32_t b1 = sVu[(k0 + 4 + lc) * 132 + d];
                mma_m16n8k8(ofr[ni], af, b0, b1);
            }
        }
    }

    const float invA = 1.f / lrow[0];
    const float invB = 1.f / lrow[1];
    float* og = O + (size_t)(b * Ss + q0) * Dd + h * HDim;
    #pragma unroll
    for (int ni = 0; ni < 8; ni++) {
        const int col = wc * 64 + ni * 8 + 2 * lc;
        float2 oA, oB;
        oA.x = rna_tf32f(ofr[ni][0] * invA);
        oA.y = rna_tf32f(ofr[ni][1] * invA);
        oB.x = rna_tf32f(ofr[ni][2] * invB);
        oB.y = rna_tf32f(ofr[ni][3] * invB);
        *(float2*)(og + (size_t)rA * Dd + col) = oA;
        *(float2*)(og + (size_t)rB * Dd + col) = oB;
    }
}

// ---------------------------------------------------------------------------
extern "C" void kernel_launch(void* const* d_in, const int* in_sizes, int n_in,
                              void* d_out, int out_size)
{
    const float* subj = (const float*)d_in[0];
    const float* obj  = (const float*)d_in[1];
    const float* wq   = (const float*)d_in[2];
    const float* bq   = (const float*)d_in[3];
    const float* wk   = (const float*)d_in[4];
    const float* bk   = (const float*)d_in[5];
    const float* wv   = (const float*)d_in[6];
    const float* bv   = (const float*)d_in[7];
    const float* wc   = (const float*)d_in[8];
    const float* bc   = (const float*)d_in[9];
    const float* base = (const float*)d_in[10];
    float* out = (float*)d_out;

    float *Q, *K, *V, *C, *As, *Ao, *Wr;
    cudaGetSymbolAddress((void**)&Q, g_Q);
    cudaGetSymbolAddress((void**)&K, g_K);
    cudaGetSymbolAddress((void**)&V, g_V);
    cudaGetSymbolAddress((void**)&C, g_C);
    cudaGetSymbolAddress((void**)&As, g_As);
    cudaGetSymbolAddress((void**)&Ao, g_Ao);
    cudaGetSymbolAddress((void**)&Wr, g_Wr);
    const size_t WSZ = (size_t)Dd * Dd;

    cudaFuncSetAttribute(gemm3_kernel,
                         cudaFuncAttributeMaxDynamicSharedMemorySize, GEMM_SMEM);
    cudaFuncSetAttribute(gemm_tc_kernel,
                         cudaFuncAttributeMaxDynamicSharedMemorySize, GEMM_SMEM);
    cudaFuncSetAttribute(flash5_kernel,
                         cudaFuncAttributeMaxDynamicSharedMemorySize, FLASH5_SMEM);

    // launch order: table(1), round(2), round(3), round4(4), gemm3(5),
    // flash5(6) <- ncu (-s 5 -c 1) captures flash5
    rope_table2_kernel<<<(64 * Ss + 255) / 256, 256>>>(base);

    const int nA4 = (int)((size_t)MROWS * Dd / 4);
    const int nW4 = (int)(WSZ / 4);
    round_tf32_kernel<<<(nA4 + 255) / 256, 256>>>(subj, As, nA4);
    round_tf32_kernel<<<(nA4 + 255) / 256, 256>>>(obj,  Ao, nA4);
    round4_kernel<<<dim3((nW4 + 255) / 256, 4), 256>>>(wq, wk, wv, wc, Wr, nW4);

    dim3 gg3(Dd / 128, MROWS / 128, 3);
    gemm3_kernel<<<gg3, 128, GEMM_SMEM>>>(As, Ao, Wr, bq, bk, bv, Q, K, V);

    flash5_kernel<<<dim3(Ss / 128, Hh, Bb), 512, FLASH5_SMEM>>>(Q, K, V, C);

    dim3 gg(Dd / 128, MROWS / 128);
    gemm_tc_kernel<<<gg, 128, GEMM_SMEM>>>(C, Wr + 3 * WSZ, bc, out, 0);
}

// round 16
// speedup vs baseline: 1.2120x; 1.0148x over previous
#include <cuda_runtime.h>
#include <cuda_bf16.h>
#include <math.h>
#include <stdint.h>

#define Bb 4
#define Ss 2048
#define Dd 2048
#define Hh 16
#define HDim 128
#define MROWS (Bb * Ss)  // 8192

// Scratch (allocation-free: device globals)
__device__ float g_Q[(size_t)Bb * Ss * Dd];
__device__ float g_K[(size_t)Bb * Ss * Dd];
__device__ float g_V[(size_t)Bb * Ss * Dd];
__device__ float g_C[(size_t)Bb * Ss * Dd];
__device__ float g_As[(size_t)MROWS * Dd];      // subj rounded to tf32
__device__ float g_Ao[(size_t)MROWS * Dd];      // obj rounded to tf32
__device__ float g_Wr[4][(size_t)Dd * Dd];      // weights rounded to tf32
__device__ float2 g_tab2[64 * Ss];              // [j][s] -> (cos, sin)

// ---------------------------------------------------------------------------
// helpers
// ---------------------------------------------------------------------------
__device__ __forceinline__ uint32_t smem_u32(const void* p) {
    uint32_t r;
    asm("{ .reg .u64 t; cvta.to.shared.u64 t, %1; cvt.u32.u64 %0, t; }"
        : "=r"(r) : "l"(p));
    return r;
}

#define CP_ASYNC16(smem, gptr) \
    asm volatile("cp.async.cg.shared.global [%0], [%1], 16;" \
                 :: "r"(smem), "l"(gptr) : "memory")
#define CP_COMMIT() asm volatile("cp.async.commit_group;" ::: "memory")
#define CP_WAIT(n)  asm volatile("cp.async.wait_group %0;" :: "n"(n) : "memory")

// pair barrier: 2 warps (64 threads), named barrier ids 1..8
#define BAR_PAIR(id) \
    asm volatile("bar.sync %0, %1;" :: "r"(id), "r"(64) : "memory")

__device__ __forceinline__ uint32_t cvt_tf32(float x) {
    uint32_t r;
    asm("cvt.rna.tf32.f32 %0, %1;" : "=r"(r) : "f"(x));
    return r;
}
__device__ __forceinline__ float rna_tf32f(float x) {
    return __uint_as_float(cvt_tf32(x));
}
__device__ __forceinline__ float ex2f(float x) {
    float r;
    asm("ex2.approx.ftz.f32 %0, %1;" : "=f"(r) : "f"(x));
    return r;
}

__device__ __forceinline__ void mma_m16n8k8(float* d, const uint32_t* a,
                                            uint32_t b0, uint32_t b1) {
    asm volatile(
        "mma.sync.aligned.m16n8k8.row.col.f32.tf32.tf32.f32 "
        "{%0,%1,%2,%3}, {%4,%5,%6,%7}, {%8,%9}, {%0,%1,%2,%3};"
        : "+f"(d[0]), "+f"(d[1]), "+f"(d[2]), "+f"(d[3])
        : "r"(a[0]), "r"(a[1]), "r"(a[2]), "r"(a[3]), "r"(b0), "r"(b1));
}

__device__ __forceinline__ void mma_bf16(float* d, const uint32_t* a,
                                         uint32_t b0, uint32_t b1) {
    asm volatile(
        "mma.sync.aligned.m16n8k16.row.col.f32.bf16.bf16.f32 "
        "{%0,%1,%2,%3}, {%4,%5,%6,%7}, {%8,%9}, {%0,%1,%2,%3};"
        : "+f"(d[0]), "+f"(d[1]), "+f"(d[2]), "+f"(d[3])
        : "r"(a[0]), "r"(a[1]), "r"(a[2]), "r"(a[3]), "r"(b0), "r"(b1));
}

// split (x,y) into packed bf16 hi pair + lo pair (x in low half)
__device__ __forceinline__ void split2(float x, float y,
                                       uint32_t& hi, uint32_t& lo) {
    __nv_bfloat162 h2 = __floats2bfloat162_rn(x, y);
    float hx = __bfloat162float(h2.x);
    float hy = __bfloat162float(h2.y);
    __nv_bfloat162 l2 = __floats2bfloat162_rn(x - hx, y - hy);
    hi = *reinterpret_cast<uint32_t*>(&h2);
    lo = *reinterpret_cast<uint32_t*>(&l2);
}

// ---------------------------------------------------------------------------
// Pre-round fp32 -> tf32-exact fp32 (RNA).
// ---------------------------------------------------------------------------
__global__ __launch_bounds__(256) void round_tf32_kernel(
    const float* __restrict__ src, float* __restrict__ dst, int n4)
{
    int i = blockIdx.x * blockDim.x + threadIdx.x;
    if (i >= n4) return;
    float4 v = ((const float4*)src)[i];
    uint4 o;
    o.x = cvt_tf32(v.x); o.y = cvt_tf32(v.y);
    o.z = cvt_tf32(v.z); o.w = cvt_tf32(v.w);
    ((uint4*)dst)[i] = o;
}

__global__ __launch_bounds__(256) void round4_kernel(
    const float* __restrict__ s0, const float* __restrict__ s1,
    const float* __restrict__ s2, const float* __restrict__ s3,
    float* __restrict__ dbase, int n4)
{
    int i = blockIdx.x * blockDim.x + threadIdx.x;
    if (i >= n4) return;
    const float* src = (blockIdx.y == 0) ? s0 : (blockIdx.y == 1) ? s1
                     : (blockIdx.y == 2) ? s2 : s3;
    float* dst = dbase + (size_t)blockIdx.y * Dd * Dd;
    float4 v = ((const float4*)src)[i];
    uint4 o;
    o.x = cvt_tf32(v.x); o.y = cvt_tf32(v.y);
    o.z = cvt_tf32(v.z); o.w = cvt_tf32(v.w);
    ((uint4*)dst)[i] = o;
}

// ---------------------------------------------------------------------------
// tf32 mma.sync GEMM core (4 warps, 64x64 warp tile, 3-stage, single barrier,
// 2 CTAs/SM) — unchanged from R15.
// ---------------------------------------------------------------------------
#define BKt 32
#define NKT (Dd / BKt)            // 64
#define GST 3
#define SA_STRIDE 36
#define SB_STRIDE 136
#define SA_WORDS (128 * SA_STRIDE)   // 4608
#define SB_WORDS (BKt * SB_STRIDE)   // 4352
#define STAGE_WORDS (SA_WORDS + SB_WORDS)
#define GEMM_SMEM (GST * STAGE_WORDS * 4)  // 107520 B

__device__ __forceinline__ void gemm_core(
    float* sm,
    const float* __restrict__ A, const float* __restrict__ W,
    const float* __restrict__ bias, float* __restrict__ C, int doRope)
{
    const int tid = threadIdx.x;
    const int wid = tid >> 5;
    const int lane = tid & 31;
    const int rowBase = blockIdx.y * 128;
    const int colBase = blockIdx.x * 128;

    const uint32_t sbase = smem_u32(sm);

    const float* aG = A + (size_t)(rowBase + (tid >> 3)) * Dd + (tid & 7) * 4;
    const float* bG = W + (size_t)(tid >> 5) * Dd + colBase + (tid & 31) * 4;
    const uint32_t aS = sbase + ((tid >> 3) * SA_STRIDE + (tid & 7) * 4) * 4;
    const uint32_t bS = sbase + (SA_WORDS + (tid >> 5) * SB_STRIDE + (tid & 31) * 4) * 4;

    const int wr = wid & 1;
    const int wc = wid >> 1;
    const int m0 = wr * 64;
    const int n0 = wc * 64;
    const int lg = lane >> 2;
    const int lc = lane & 3;

    float acc[4][8][4];
    #pragma unroll
    for (int mi = 0; mi < 4; mi++)
        #pragma unroll
        for (int ni = 0; ni < 8; ni++)
            #pragma unroll
            for (int r = 0; r < 4; r++) acc[mi][ni][r] = 0.f;

    #pragma unroll
    for (int p = 0; p < 2; p++) {
        const float* ag = aG + p * BKt;
        const float* bg = bG + (size_t)p * BKt * Dd;
        const uint32_t as = aS + p * STAGE_WORDS * 4;
        const uint32_t bs = bS + p * STAGE_WORDS * 4;
        #pragma unroll
        for (int i = 0; i < 8; i++) {
            CP_ASYNC16(as + i * 16 * SA_STRIDE * 4, ag + (size_t)(16 * i) * Dd);
            CP_ASYNC16(bs + i * 4 * SB_STRIDE * 4,  bg + (size_t)(4 * i) * Dd);
        }
        CP_COMMIT();
    }

    int s = 0;
    for (int kt = 0; kt < NKT; kt++) {
        if (kt + 1 < NKT) { CP_WAIT(1); } else { CP_WAIT(0); }
        __syncthreads();

        if (kt + 2 < NKT) {
            int s2 = s + 2; if (s2 >= GST) s2 -= GST;
            const float* ag = aG + (kt + 2) * BKt;
            const float* bg = bG + (size_t)(kt + 2) * BKt * Dd;
            const uint32_t as = aS + s2 * STAGE_WORDS * 4;
            const uint32_t bs = bS + s2 * STAGE_WORDS * 4;
            #pragma unroll
            for (int i = 0; i < 8; i++) {
                CP_ASYNC16(as + i * 16 * SA_STRIDE * 4, ag + (size_t)(16 * i) * Dd);
                CP_ASYNC16(bs + i * 4 * SB_STRIDE * 4,  bg + (size_t)(4 * i) * Dd);
            }
            CP_COMMIT();
        }

        const uint32_t* sAp = (const uint32_t*)(sm + s * STAGE_WORDS);
        const uint32_t* sBp = sAp + SA_WORDS;

        #pragma unroll
        for (int ks = 0; ks < 4; ks++) {
            const int k0 = ks * 8;
            uint32_t afr[4][4];
            #pragma unroll
            for (int mi = 0; mi < 4; mi++) {
                const int r = m0 + mi * 16 + lg;
                const int c = k0 + lc;
                afr[mi][0] = sAp[r * SA_STRIDE + c];
                afr[mi][1] = sAp[(r + 8) * SA_STRIDE + c];
                afr[mi][2] = sAp[r * SA_STRIDE + c + 4];
                afr[mi][3] = sAp[(r + 8) * SA_STRIDE + c + 4];
            }
            #pragma unroll
            for (int ni = 0; ni < 8; ni++) {
                const int col = n0 + ni * 8 + lg;
                uint32_t b0 = sBp[(k0 + lc) * SB_STRIDE + col];
                uint32_t b1 = sBp[(k0 + 4 + lc) * SB_STRIDE + col];
                #pragma unroll
                for (int mi = 0; mi < 4; mi++)
                    mma_m16n8k8(acc[mi][ni], afr[mi], b0, b1);
            }
        }
        if (++s >= GST) s -= GST;
    }

    #pragma unroll
    for (int mi = 0; mi < 4; mi++) {
        const int row = rowBase + m0 + mi * 16 + lg;
        #pragma unroll
        for (int ni = 0; ni < 8; ni++) {
            const int col = colBase + n0 + ni * 8 + 2 * lc;
            const float bv0 = __ldg(bias + col);
            const float bv1 = __ldg(bias + col + 1);
            const int jn = (col & 127) >> 1;

            #pragma unroll
            for (int half = 0; half < 2; half++) {
                const int r = row + half * 8;
                float x0 = acc[mi][ni][2 * half]     + bv0;
                float x1 = acc[mi][ni][2 * half + 1] + bv1;
                if (doRope) {
                    float2 cs = g_tab2[jn * Ss + (r & (Ss - 1))];
                    float y0 = x0 * cs.x - x1 * cs.y;
                    float y1 = x0 * cs.y + x1 * cs.x;
                    x0 = y0; x1 = y1;
                }
                *(float2*)(C + (size_t)r * Dd + col) = make_float2(x0, x1);
            }
        }
    }
}

__global__ __launch_bounds__(128, 2) void gemm3_kernel(
    const float* __restrict__ As, const float* __restrict__ Ao,
    const float* __restrict__ Wr,
    const float* __restrict__ bq, const float* __restrict__ bk,
    const float* __restrict__ bv,
    float* __restrict__ Q, float* __restrict__ K, float* __restrict__ V)
{
    extern __shared__ float sm[];
    const int z = blockIdx.z;
    const float* A = (z == 0) ? As : Ao;
    const float* W = Wr + (size_t)z * Dd * Dd;
    const float* bias = (z == 0) ? bq : (z == 1) ? bk : bv;
    float* C = (z == 0) ? Q : (z == 1) ? K : V;
    gemm_core(sm, A, W, bias, C, (z < 2) ? 1 : 0);
}

__global__ __launch_bounds__(128, 2) void gemm_tc_kernel(
    const float* __restrict__ A, const float* __restrict__ W,
    const float* __restrict__ bias, float* __restrict__ C, int doRope)
{
    extern __shared__ float sm[];
    gemm_core(sm, A, W, bias, C, doRope);
}

// ---------------------------------------------------------------------------
// RoPE cos/sin table (fp64 for angle accuracy), layout [j][s]
// ---------------------------------------------------------------------------
__global__ void rope_table2_kernel(const float* __restrict__ base_p)
{
    int t = blockIdx.x * blockDim.x + threadIdx.x;
    if (t >= 64 * Ss) return;
    int j = t >> 11, s = t & (Ss - 1);
    double base = (double)(*base_p);
    double f = exp(-(double)j / 64.0 * log(base));
    double ang = (double)s * f;
    double sn, cs;
    sincos(ang, &sn, &cs);
    g_tab2[t] = make_float2((float)cs, (float)sn);
}

// ---------------------------------------------------------------------------
// Flash attention v6 = v5 with:
//  - log2-domain softmax: log2(e)/sqrt(128) folded into Q scale; all exps
//    are bare ex2.approx (saves the FMUL inside every __expf, incl. alphas)
//  - the two softmax reduction barriers are PAIR-scoped named barriers
//    (warps w and w+8 share row group wr): bar.sync 1+wr, 64
//    -> 4 full 512-thread barriers/iter become 2 full + 2 cheap pair bars.
// ---------------------------------------------------------------------------
#define F4_QHI 0
#define F4_QLO (F4_QHI + 128 * 68)
#define F4_KHI (F4_QLO + 128 * 68)
#define F4_KLO (F4_KHI + 64 * 68)
#define F4_V   (F4_KLO + 64 * 68)     // V[t][d] tf32 fp32, stride 132
#define F4_P   (F4_V + 64 * 132)      // P[row][t] tf32 fp32, stride 68
#define F4_RM  (F4_P + 128 * 68)
#define F4_RS  (F4_RM + 256)
#define F4_WORDS (F4_RS + 256)
#define FLASH6_SMEM (F4_WORDS * 4)    // 175104 B

__global__ __launch_bounds__(512, 1) void flash6_kernel(
    const float* __restrict__ Q, const float* __restrict__ K,
    const float* __restrict__ V, float* __restrict__ O)
{
    extern __shared__ uint32_t smw[];
    float* sRedM = (float*)(smw + F4_RM);
    float* sRedS = (float*)(smw + F4_RS);
    float* sP = (float*)(smw + F4_P);

    const int qt = (Ss / 128 - 1) - blockIdx.x;   // big CTAs first
    const int h = blockIdx.y, b = blockIdx.z;
    const int tid = threadIdx.x;
    const int w = tid >> 5, lane = tid & 31;
    const int lg = lane >> 2, lc = lane & 3;
    const int wr = w & 7, wc = w >> 3;
    const int m0 = wr * 16;
    const int q0 = qt * 128;
    // log2(e)/sqrt(128): scores in log2 units
    const float scale2 = 0.08838834764831845f * 1.4426950408889634f;
    const int barId = 1 + wr;       // named barrier for this row-group pair

    const int rA = m0 + lg;
    const int rB = m0 + lg + 8;
    const int gRA = q0 + rA;
    const int gRB = q0 + rB;

    // K/V prefetch mappings (registers)
    const int krow = tid >> 3;                 // 0..63
    const int kc8 = tid & 7;
    const int vrow0 = tid >> 5;                // 0..15
    const int vf4 = tid & 31;
    const float* kgBase = K + (size_t)(b * Ss) * Dd + h * HDim;
    const float* vgBase = V + (size_t)(b * Ss) * Dd + h * HDim;

    float4 kreg[4], vreg[4];
    {   // prologue: tile 0 into registers
        const float* kg = kgBase + (size_t)krow * Dd;
        #pragma unroll
        for (int i = 0; i < 4; i++)
            kreg[i] = *(const float4*)(kg + (kc8 + 8 * i) * 4);
        #pragma unroll
        for (int i = 0; i < 4; i++)
            vreg[i] = *(const float4*)(vgBase + (size_t)(vrow0 + 16 * i) * Dd + vf4 * 4);
    }

    // --- load Q tile (128x128), scale (log2 domain) + split bf16 hi/lo ---
    {
        const int row = tid >> 2;
        const float* qg = Q + (size_t)(b * Ss + q0 + row) * Dd + h * HDim;
        #pragma unroll
        for (int i = 0; i < 8; i++) {
            const int c4 = (tid & 3) + 4 * i;
            float4 v = *(const float4*)(qg + c4 * 4);
            v.x *= scale2; v.y *= scale2; v.z *= scale2; v.w *= scale2;
            uint32_t h0, l0, h1, l1;
            split2(v.x, v.y, h0, l0);
            split2(v.z, v.w, h1, l1);
            const int dp = c4 * 2;
            smw[F4_QHI + row * 68 + dp]     = h0;
            smw[F4_QHI + row * 68 + dp + 1] = h1;
            smw[F4_QLO + row * 68 + dp]     = l0;
            smw[F4_QLO + row * 68 + dp + 1] = l1;
        }
    }

    float mrow[2] = {-1e30f, -1e30f};
    float lrow[2] = {0.f, 0.f};
    float ofr[8][4];
    #pragma unroll
    for (int n = 0; n < 8; n++)
        #pragma unroll
        for (int r = 0; r < 4; r++) ofr[n][r] = 0.f;

    const int ktEnd = 2 * qt + 1;
    for (int kt = 0; kt <= ktEnd; kt++) {
        __syncthreads();   // prev iter reads of sK/sV done; Q store done

        // --- store tile kt from registers: K split, V tf32 ---
        #pragma unroll
        for (int i = 0; i < 4; i++) {
            float4 v = kreg[i];
            uint32_t h0, l0, h1, l1;
            split2(v.x, v.y, h0, l0);
            split2(v.z, v.w, h1, l1);
            const int dp = (kc8 + 8 * i) * 2;
            smw[F4_KHI + krow * 68 + dp]     = h0;
            smw[F4_KHI + krow * 68 + dp + 1] = h1;
            smw[F4_KLO + krow * 68 + dp]     = l0;
            smw[F4_KLO + krow * 68 + dp + 1] = l1;
        }
        #pragma unroll
        for (int i = 0; i < 4; i++) {
            const int row = vrow0 + 16 * i;
            float4 v = vreg[i];
            uint4 o;
            o.x = cvt_tf32(v.x); o.y = cvt_tf32(v.y);
            o.z = cvt_tf32(v.z); o.w = cvt_tf32(v.w);
            *(uint4*)&smw[F4_V + row * 132 + vf4 * 4] = o;
        }
        __syncthreads();

        // --- prefetch tile kt+1 into registers (latency hidden by compute)
        if (kt < ktEnd) {
            const float* kg = kgBase + (size_t)((kt + 1) * 64 + krow) * Dd;
            #pragma unroll
            for (int i = 0; i < 4; i++)
                kreg[i] = *(const float4*)(kg + (kc8 + 8 * i) * 4);
            const float* vg = vgBase + (size_t)((kt + 1) * 64) * Dd;
            #pragma unroll
            for (int i = 0; i < 4; i++)
                vreg[i] = *(const float4*)(vg + (size_t)(vrow0 + 16 * i) * Dd + vf4 * 4);
        }

        // --- S = Q @ K^T (3-term bf16): rows m0..+15, cols wc*32..+31
        float sfr[4][4];
        #pragma unroll
        for (int n = 0; n < 4; n++)
            #pragma unroll
            for (int r = 0; r < 4; r++) sfr[n][r] = 0.f;

        #pragma unroll
        for (int ks = 0; ks < 8; ks++) {
            const int kp = ks * 8;
            uint32_t ah[4], al[4];
            ah[0] = smw[F4_QHI + rA * 68 + kp + lc];
            ah[1] = smw[F4_QHI + rB * 68 + kp + lc];
            ah[2] = smw[F4_QHI + rA * 68 + kp + lc + 4];
            ah[3] = smw[F4_QHI + rB * 68 + kp + lc + 4];
            al[0] = smw[F4_QLO + rA * 68 + kp + lc];
            al[1] = smw[F4_QLO + rB * 68 + kp + lc];
            al[2] = smw[F4_QLO + rA * 68 + kp + lc + 4];
            al[3] = smw[F4_QLO + rB * 68 + kp + lc + 4];
            #pragma unroll
            for (int ni = 0; ni < 4; ni++) {
                const int j = wc * 32 + ni * 8 + lg;
                uint32_t bh0 = smw[F4_KHI + j * 68 + kp + lc];
                uint32_t bh1 = smw[F4_KHI + j * 68 + kp + lc + 4];
                uint32_t bl0 = smw[F4_KLO + j * 68 + kp + lc];
                uint32_t bl1 = smw[F4_KLO + j * 68 + kp + lc + 4];
                mma_bf16(sfr[ni], ah, bh0, bh1);
                mma_bf16(sfr[ni], ah, bl0, bl1);
                mma_bf16(sfr[ni], al, bh0, bh1);
            }
        }

        // --- online softmax on C-fragments (log2 domain) ---
        const bool diag = (kt >= 2 * qt);
        float vA = -1e30f, vB = -1e30f;
        #pragma unroll
        for (int ni = 0; ni < 4; ni++) {
            if (diag) {
                const int gc0 = kt * 64 + wc * 32 + ni * 8 + 2 * lc;
                if (gc0 > gRA)     sfr[ni][0] = -1e30f;
                if (gc0 + 1 > gRA) sfr[ni][1] = -1e30f;
                if (gc0 > gRB)     sfr[ni][2] = -1e30f;
                if (gc0 + 1 > gRB) sfr[ni][3] = -1e30f;
            }
            vA = fmaxf(vA, fmaxf(sfr[ni][0], sfr[ni][1]));
            vB = fmaxf(vB, fmaxf(sfr[ni][2], sfr[ni][3]));
        }
        vA = fmaxf(vA, __shfl_xor_sync(0xffffffffu, vA, 1));
        vA = fmaxf(vA, __shfl_xor_sync(0xffffffffu, vA, 2));
        vB = fmaxf(vB, __shfl_xor_sync(0xffffffffu, vB, 1));
        vB = fmaxf(vB, __shfl_xor_sync(0xffffffffu, vB, 2));
        if (lc == 0) {
            sRedM[wc * 128 + rA] = vA;
            sRedM[wc * 128 + rB] = vB;
        }
        BAR_PAIR(barId);   // pair-scope: only warps wc=0/1 of row group wr
        const float mtA = fmaxf(sRedM[rA], sRedM[128 + rA]);
        const float mtB = fmaxf(sRedM[rB], sRedM[128 + rB]);
        const float mnA = fmaxf(mrow[0], mtA);
        const float mnB = fmaxf(mrow[1], mtB);
        const float alA = ex2f(mrow[0] - mnA);
        const float alB = ex2f(mrow[1] - mnB);

        float sumA = 0.f, sumB = 0.f;
        #pragma unroll
        for (int ni = 0; ni < 4; ni++) {
            float p0 = rna_tf32f(ex2f(sfr[ni][0] - mnA));
            float p1 = rna_tf32f(ex2f(sfr[ni][1] - mnA));
            float p2 = rna_tf32f(ex2f(sfr[ni][2] - mnB));
            float p3 = rna_tf32f(ex2f(sfr[ni][3] - mnB));
            sumA += p0 + p1;
            sumB += p2 + p3;
            const int t0 = wc * 32 + ni * 8 + 2 * lc;
            *(float2*)&sP[rA * 68 + t0] = make_float2(p0, p1);
            *(float2*)&sP[rB * 68 + t0] = make_float2(p2, p3);
        }
        sumA += __shfl_xor_sync(0xffffffffu, sumA, 1);
        sumA += __shfl_xor_sync(0xffffffffu, sumA, 2);
        sumB += __shfl_xor_sync(0xffffffffu, sumB, 1);
        sumB += __shfl_xor_sync(0xffffffffu, sumB, 2);
        if (lc == 0) {
            sRedS[wc * 128 + rA] = sumA;
            sRedS[wc * 128 + rB] = sumB;
        }
        BAR_PAIR(barId);   // publishes sums and P rows of this pair
        lrow[0] = lrow[0] * alA + sRedS[rA] + sRedS[128 + rA];
        lrow[1] = lrow[1] * alB + sRedS[rB] + sRedS[128 + rB];
        mrow[0] = mnA;
        mrow[1] = mnB;
        #pragma unroll
        for (int n = 0; n < 8; n++) {
            ofr[n][0] *= alA; ofr[n][1] *= alA;
            ofr[n][2] *= alB; ofr[n][3] *= alB;
        }

        // --- O += P @ V (tf32): rows m0..+15, d-cols wc*64..+63
        const uint32_t* sPu = (const uint32_t*)sP;
        const uint32_t* sVu = smw + F4_V;
        #pragma unroll
        for (int ks2 = 0; ks2 < 8; ks2++) {
            const int k0 = ks2 * 8;
            uint32_t af[4];
            af[0] = sPu[rA * 68 + k0 + lc];
            af[1] = sPu[rB * 68 + k0 + lc];
            af[2] = sPu[rA * 68 + k0 + lc + 4];
            af[3] = sPu[rB * 68 + k0 + lc + 4];
            #pragma unroll
            for (int ni = 0; ni < 8; ni++) {
                const int d = wc * 64 + ni * 8 + lg;
                uint32_t b0 = sVu[(k0 + lc) * 132 + d];
                uint32_t b1 = sVu[(k0 + 4 + lc) * 132 + d];
                mma_m16n8k8(ofr[ni], af, b0, b1);
            }
        }
    }

    const float invA = 1.f / lrow[0];
    const float invB = 1.f / lrow[1];
    float* og = O + (size_t)(b * Ss + q0) * Dd + h * HDim;
    #pragma unroll
    for (int ni = 0; ni < 8; ni++) {
        const int col = wc * 64 + ni * 8 + 2 * lc;
        float2 oA, oB;
        oA.x = rna_tf32f(ofr[ni][0] * invA);
        oA.y = rna_tf32f(ofr[ni][1] * invA);
        oB.x = rna_tf32f(ofr[ni][2] * invB);
        oB.y = rna_tf32f(ofr[ni][3] * invB);
        *(float2*)(og + (size_t)rA * Dd + col) = oA;
        *(float2*)(og + (size_t)rB * Dd + col) = oB;
    }
}

// ---------------------------------------------------------------------------
extern "C" void kernel_launch(void* const* d_in, const int* in_sizes, int n_in,
                              void* d_out, int out_size)
{
    const float* subj = (const float*)d_in[0];
    const float* obj  = (const float*)d_in[1];
    const float* wq   = (const float*)d_in[2];
    const float* bq   = (const float*)d_in[3];
    const float* wk   = (const float*)d_in[4];
    const float* bk   = (const float*)d_in[5];
    const float* wv   = (const float*)d_in[6];
    const float* bv   = (const float*)d_in[7];
    const float* wc   = (const float*)d_in[8];
    const float* bc   = (const float*)d_in[9];
    const float* base = (const float*)d_in[10];
    float* out = (float*)d_out;

    float *Q, *K, *V, *C, *As, *Ao, *Wr;
    cudaGetSymbolAddress((void**)&Q, g_Q);
    cudaGetSymbolAddress((void**)&K, g_K);
    cudaGetSymbolAddress((void**)&V, g_V);
    cudaGetSymbolAddress((void**)&C, g_C);
    cudaGetSymbolAddress((void**)&As, g_As);
    cudaGetSymbolAddress((void**)&Ao, g_Ao);
    cudaGetSymbolAddress((void**)&Wr, g_Wr);
    const size_t WSZ = (size_t)Dd * Dd;

    cudaFuncSetAttribute(gemm3_kernel,
                         cudaFuncAttributeMaxDynamicSharedMemorySize, GEMM_SMEM);
    cudaFuncSetAttribute(gemm_tc_kernel,
                         cudaFuncAttributeMaxDynamicSharedMemorySize, GEMM_SMEM);
    cudaFuncSetAttribute(flash6_kernel,
                         cudaFuncAttributeMaxDynamicSharedMemorySize, FLASH6_SMEM);

    rope_table2_kernel<<<(64 * Ss + 255) / 256, 256>>>(base);

    const int nA4 = (int)((size_t)MROWS * Dd / 4);
    const int nW4 = (int)(WSZ / 4);
    round_tf32_kernel<<<(nA4 + 255) / 256, 256>>>(subj, As, nA4);
    round_tf32_kernel<<<(nA4 + 255) / 256, 256>>>(obj,  Ao, nA4);
    round4_kernel<<<dim3((nW4 + 255) / 256, 4), 256>>>(wq, wk, wv, wc, Wr, nW4);

    dim3 gg3(Dd / 128, MROWS / 128, 3);
    gemm3_kernel<<<gg3, 128, GEMM_SMEM>>>(As, Ao, Wr, bq, bk, bv, Q, K, V);

    flash6_kernel<<<dim3(Ss / 128, Hh, Bb), 512, FLASH6_SMEM>>>(Q, K, V, C);

    dim3 gg(Dd / 128, MROWS / 128);
    gemm_tc_kernel<<<gg, 128, GEMM_SMEM>>>(C, Wr + 3 * WSZ, bc, out, 0);
}